// round 15
// baseline (speedup 1.0000x reference)
#include <cuda_runtime.h>
#include <cuda_fp16.h>
#include <cstdint>
#include <math.h>

// Problem dims
#define BB   8
#define SS   1024
#define EE   512
#define II   1024
#define HH   4
#define DHH  256
#define KKC  4
#define BSR  (BB*SS)          // 8192 rows
#define EPS  1e-5f

// ---------------- scratch (static device memory; rewritten every call) ----------
__device__ __half g_xn16[BSR*EE];         // fp16 LN out (up GEMM A)
__device__ __half g_up16[BSR*2048];       // fp16 up out: x_m cols [0,1024), z cols [1024,2048)
__device__ float g_cact[BSR*II];          // fp32 (headgate skip)
__device__ __half g_ca16[BSR*II];         // fp16 conv act (qk GEMM A)
__device__ __half g_qk16[BSR*2048];       // fp16 q|k (attn + gates), stride 2048
__device__ __half g_v16[BSR*II];          // fp16 v (vtrans + gates)
__device__ float g_h   [BSR*II];          // attn out (fp32)
__device__ __half g_h16[BSR*II];          // headgate out (down GEMM A)
__device__ float g_x1  [BSR*EE];          // fp32 residual stream
__device__ __half g_x116[BSR*EE];         // fp16 copy (fin GEMM A)
__device__ float g_ipre[BB*HH*SS];
__device__ float g_fpre[BB*HH*SS];
__device__ float g_u   [BB*HH*SS];
__device__ float g_mx  [BB*HH*SS];
__device__ float g_mm  [BB*HH*SS];
__device__ __half g_vT [32*256*1024];     // V^T per (b,h), fp16 (16MB)
__device__ __half g_w16[9502720];         // fp16 weights, transposed layouts

__device__ __forceinline__ uint32_t smem_u32(const void* p) {
    uint32_t a;
    asm("{ .reg .u64 t; cvta.to.shared.u64 t, %1; cvt.u32.u64 %0, t; }" : "=r"(a) : "l"(p));
    return a;
}
__device__ __forceinline__ void cp_async16(uint32_t dst, const void* src) {
    asm volatile("cp.async.cg.shared.global [%0], [%1], 16;" :: "r"(dst), "l"(src));
}
#define CP_COMMIT() asm volatile("cp.async.commit_group;" ::: "memory")
#define CP_WAIT1()  asm volatile("cp.async.wait_group 1;"  ::: "memory")
#define CP_WAIT0()  asm volatile("cp.async.wait_group 0;"  ::: "memory")

__device__ __forceinline__ void mma_f16(float* d, const uint32_t* a, uint32_t b0, uint32_t b1) {
    asm volatile("mma.sync.aligned.m16n8k16.row.col.f32.f16.f16.f32 "
        "{%0,%1,%2,%3}, {%4,%5,%6,%7}, {%8,%9}, {%0,%1,%2,%3};"
        : "+f"(d[0]), "+f"(d[1]), "+f"(d[2]), "+f"(d[3])
        : "r"(a[0]), "r"(a[1]), "r"(a[2]), "r"(a[3]), "r"(b0), "r"(b1));
}
#define LDSM_X4(r, addr) \
    asm volatile("ldmatrix.sync.aligned.m8n8.x4.shared.b16 {%0,%1,%2,%3}, [%4];" \
        : "=r"((r)[0]), "=r"((r)[1]), "=r"((r)[2]), "=r"((r)[3]) : "r"(addr))

// ================= fp16 mma.sync GEMM, cp.async 3-stage, ldmatrix ==============
__device__ __forceinline__ uint32_t sw_off(int r, int c) {
    return (uint32_t)(((r >> 1) << 7) + (((((r & 1) << 2) + c) ^ ((r >> 1) & 7)) << 4));
}

__device__ __forceinline__ void issue_tile16(uint32_t sA, uint32_t sB,
        const __half* A, int lda, const __half* BT, int ldb,
        int row0, int col0, int k0, int tid)
{
    const __half* Ag = A + (size_t)row0 * lda + k0;
    const __half* Bg = BT + (size_t)col0 * ldb + k0;
    #pragma unroll
    for (int j = 0; j < 2; j++) {
        int i = tid + 256 * j;
        int r = i >> 2, c = i & 3;
        cp_async16(sA + sw_off(r, c), Ag + (size_t)r * lda + (c << 3));
    }
    #pragma unroll
    for (int j = 0; j < 2; j++) {
        int i = tid + 256 * j;
        int r = i >> 2, c = i & 3;
        cp_async16(sB + sw_off(r, c), Bg + (size_t)r * ldb + (c << 3));
    }
}

__device__ __forceinline__ void compute_tile16(uint32_t sA, uint32_t sB,
        float d[4][4][4], int warp_m, int warp_n, int lane)
{
    int aRow = lane & 15, aCs = lane >> 4;
    int bRow = (lane & 7) | ((lane >> 1) & 8), bCs = (lane >> 3) & 1;
    uint32_t aBase = sA + (uint32_t)(warp_m * 4096) + sw_off(aRow, aCs);
    uint32_t bBase = sB + (uint32_t)(warp_n * 2048) + sw_off(bRow, bCs);
    #pragma unroll
    for (int ks = 0; ks < 2; ks++) {
        uint32_t kx = (uint32_t)(ks << 5);
        uint32_t a[4][4], b[2][4];
        #pragma unroll
        for (int mf = 0; mf < 4; mf++)
            LDSM_X4(a[mf], (aBase + mf * 1024) ^ kx);
        LDSM_X4(b[0], bBase ^ kx);
        LDSM_X4(b[1], (bBase + 1024) ^ kx);
        #pragma unroll
        for (int mf = 0; mf < 4; mf++) {
            mma_f16(d[mf][0], a[mf], b[0][0], b[0][1]);
            mma_f16(d[mf][1], a[mf], b[0][2], b[0][3]);
            mma_f16(d[mf][2], a[mf], b[1][0], b[1][1]);
            mma_f16(d[mf][3], a[mf], b[1][2], b[1][3]);
        }
    }
}

#define GEMM_SMEM (3 * 16384)

__global__ __launch_bounds__(256) void hgemm_kernel(
    const __half* __restrict__ A, int lda,
    const __half* __restrict__ BT, int ldb,   // [N,K]
    float* __restrict__ C, int ldc, int K,
    const float* __restrict__ bias,
    const float* __restrict__ res, int ldres,
    __half* __restrict__ C2h)
{
    extern __shared__ __align__(128) char sm[];
    uint32_t sbase = smem_u32(sm);

    int tid = threadIdx.x;
    int wid = tid >> 5, lane = tid & 31;
    int laneR = lane >> 2, laneC = lane & 3;
    int warp_m = wid & 1, warp_n = wid >> 1;
    int row0 = blockIdx.y * 128, col0 = blockIdx.x * 128;

    float d[4][4][4];
    #pragma unroll
    for (int i = 0; i < 4; i++)
        #pragma unroll
        for (int j = 0; j < 4; j++)
            #pragma unroll
            for (int u = 0; u < 4; u++) d[i][j][u] = 0.f;

    const int NK = K >> 5;

    issue_tile16(sbase, sbase + 8192, A, lda, BT, ldb, row0, col0, 0, tid);
    CP_COMMIT();
    issue_tile16(sbase + 16384, sbase + 24576, A, lda, BT, ldb, row0, col0, 32, tid);
    CP_COMMIT();

    #pragma unroll 1
    for (int kt = 0; kt < NK; kt++) {
        CP_WAIT1();
        __syncthreads();
        if (kt + 2 < NK) {
            uint32_t s = (uint32_t)((kt + 2) % 3) * 16384;
            issue_tile16(sbase + s, sbase + s + 8192,
                         A, lda, BT, ldb, row0, col0, (kt + 2) << 5, tid);
        }
        CP_COMMIT();
        uint32_t b = (uint32_t)(kt % 3) * 16384;
        compute_tile16(sbase + b, sbase + b + 8192, d, warp_m, warp_n, lane);
    }

    #pragma unroll
    for (int mf = 0; mf < 4; mf++) {
        int r = row0 + warp_m * 64 + mf * 16 + laneR;
        #pragma unroll
        for (int nf = 0; nf < 4; nf++) {
            int cc = col0 + warp_n * 32 + nf * 8 + 2 * laneC;
            float2 v0 = make_float2(d[mf][nf][0], d[mf][nf][1]);
            float2 v1 = make_float2(d[mf][nf][2], d[mf][nf][3]);
            if (bias) {
                float2 bv = *(const float2*)(bias + cc);
                v0.x += bv.x; v0.y += bv.y;
                v1.x += bv.x; v1.y += bv.y;
            }
            if (res) {
                float2 r0 = *(const float2*)(res + (size_t)r * ldres + cc);
                float2 r1 = *(const float2*)(res + (size_t)(r + 8) * ldres + cc);
                v0.x += r0.x; v0.y += r0.y;
                v1.x += r1.x; v1.y += r1.y;
            }
            if (C) {
                *(float2*)(C + (size_t)r * ldc + cc)       = v0;
                *(float2*)(C + (size_t)(r + 8) * ldc + cc) = v1;
            }
            if (C2h) {
                *(__half2*)(C2h + (size_t)r * ldc + cc)       = __floats2half2_rn(v0.x, v0.y);
                *(__half2*)(C2h + (size_t)(r + 8) * ldc + cc) = __floats2half2_rn(v1.x, v1.y);
            }
        }
    }
}

// ---------------- fused weight transpose+convert ------------------------------
__global__ __launch_bounds__(256) void wtrans_all_kernel(
    const float* __restrict__ w_up, const float* __restrict__ wq,
    const float* __restrict__ wk,  const float* __restrict__ wv,
    const float* __restrict__ w_down, const float* __restrict__ w_fin,
    __half* __restrict__ w16)
{
    int bid = blockIdx.x;
    const float* in; __half* out; int K, N, loc;
    if (bid < 9216) {
        int l = bid / 4608, r = bid % 4608;
        if (r < 1024)      { in = w_up   + (size_t)l*1048576; out = w16 + (size_t)l*1048576;                     K = 512;  N = 2048; loc = r; }
        else if (r < 2048) { in = wq     + (size_t)l*1048576; out = w16 + 2097152 + (size_t)l*2097152;           K = 1024; N = 1024; loc = r - 1024; }
        else if (r < 3072) { in = wk     + (size_t)l*1048576; out = w16 + 2097152 + (size_t)l*2097152 + 1048576; K = 1024; N = 1024; loc = r - 2048; }
        else if (r < 4096) { in = wv     + (size_t)l*1048576; out = w16 + 6291456 + (size_t)l*1048576;           K = 1024; N = 1024; loc = r - 3072; }
        else               { in = w_down + (size_t)l*524288;  out = w16 + 8388608 + (size_t)l*524288;            K = 1024; N = 512;  loc = r - 4096; }
    } else {
        in = w_fin; out = w16 + 9437184; K = 512; N = 128; loc = bid - 9216;
    }
    int nw = N >> 5;
    int nb = (loc % nw) * 32, kb = (loc / nw) * 32;
    __shared__ float t[32][33];
    int tx = threadIdx.x & 31, ty = threadIdx.x >> 5;
    #pragma unroll
    for (int j = 0; j < 32; j += 8)
        t[ty + j][tx] = in[(size_t)(kb + ty + j) * N + nb + tx];
    __syncthreads();
    #pragma unroll
    for (int j = 0; j < 32; j += 8)
        out[(size_t)(nb + ty + j) * K + kb + tx] = __float2half_rn(t[tx][ty + j]);
}

// ---------------- V transpose per (b,h): g_v16 -> g_vT[bh][d][t], fp16 ---------
__global__ __launch_bounds__(256) void vtrans_kernel(__half* __restrict__ vT)
{
    __shared__ __half t[32][36];
    int bh = blockIdx.z;
    int b = bh >> 2, h = bh & 3;
    int t0 = blockIdx.x * 32, d0 = blockIdx.y * 32;
    int tx = threadIdx.x & 31, ty = threadIdx.x >> 5;
    #pragma unroll
    for (int j = 0; j < 32; j += 8)
        t[ty + j][tx] = g_v16[(size_t)(b * SS + t0 + ty + j) * II + h * DHH + d0 + tx];
    __syncthreads();
    #pragma unroll
    for (int j = 0; j < 32; j += 8)
        vT[((size_t)bh * DHH + d0 + ty + j) * SS + t0 + tx] = t[tx][ty + j];
}

// ---------------- LayerNorm over E=512 (stores fp16) ---------------------------
__global__ __launch_bounds__(256) void ln_kernel(const float* __restrict__ x,
                                                 const float* __restrict__ g,
                                                 const float* __restrict__ b,
                                                 __half* __restrict__ y)
{
    int row = blockIdx.x;
    const float* xr = x + (size_t)row * EE;
    int c2 = threadIdx.x * 2;
    float2 xv = *(const float2*)(xr + c2);
    float s = xv.x + xv.y, s2 = xv.x*xv.x + xv.y*xv.y;
    __shared__ float sh[64];
    for (int o = 16; o; o >>= 1) {
        s  += __shfl_down_sync(0xffffffffu, s,  o);
        s2 += __shfl_down_sync(0xffffffffu, s2, o);
    }
    int wid = threadIdx.x >> 5, lane = threadIdx.x & 31;
    if (lane == 0) { sh[wid] = s; sh[32+wid] = s2; }
    __syncthreads();
    if (threadIdx.x == 0) {
        float ts = 0.f, ts2 = 0.f;
        for (int w = 0; w < 8; w++) { ts += sh[w]; ts2 += sh[32+w]; }
        sh[0] = ts; sh[32] = ts2;
    }
    __syncthreads();
    float mu  = sh[0]  * (1.f/EE);
    float var = sh[32] * (1.f/EE) - mu*mu;
    float rstd = rsqrtf(var + EPS);
    float2 gv = *(const float2*)(g + c2);
    float2 bv = *(const float2*)(b + c2);
    *(__half2*)(y + (size_t)row * EE + c2) =
        __floats2half2_rn((xv.x - mu) * rstd * gv.x + bv.x,
                          (xv.y - mu) * rstd * gv.y + bv.y);
}

// ---------------- causal depthwise conv (K=4) + SiLU, fp16 in, 4 ch/thread -----
__global__ __launch_bounds__(256) void conv_silu_kernel(const float* __restrict__ cw,
                                                        const float* __restrict__ cb)
{
    int idx = blockIdx.x * 256 + threadIdx.x;
    int c4  = (idx & 255) << 2;
    int row = idx >> 8;
    int t   = row & (SS - 1);
    const __half* base = g_up16 + (size_t)row * 2048 + c4;
    float4 acc = *(const float4*)(cb + c4);
    #pragma unroll
    for (int j = 0; j < KKC; j++) {
        int tt = t - (KKC - 1) + j;
        if (tt >= 0) {
            const __half2* xp = (const __half2*)(base + (j - (KKC - 1)) * 2048);
            float2 x01 = __half22float2(xp[0]);
            float2 x23 = __half22float2(xp[1]);
            float4 wv = *(const float4*)(cw + j * II + c4);
            acc.x = fmaf(x01.x, wv.x, acc.x);
            acc.y = fmaf(x01.y, wv.y, acc.y);
            acc.z = fmaf(x23.x, wv.z, acc.z);
            acc.w = fmaf(x23.y, wv.w, acc.w);
        }
    }
    float4 sv;
    sv.x = acc.x / (1.f + __expf(-acc.x));
    sv.y = acc.y / (1.f + __expf(-acc.y));
    sv.z = acc.z / (1.f + __expf(-acc.z));
    sv.w = acc.w / (1.f + __expf(-acc.w));
    size_t o = (size_t)row * II + c4;
    *(float4*)(g_cact + o) = sv;
    __half2* p = (__half2*)(g_ca16 + o);
    p[0] = __floats2half2_rn(sv.x, sv.y);
    p[1] = __floats2half2_rn(sv.z, sv.w);
}

// ---------------- gate projections: 16 rows/block, weights staged in smem ------
// smem: wi [3072][4] fp32 (48KB) | wf [3072][4] fp32 (48KB) = 96KB dynamic
#define GROWS 16
#define GATES_SMEM 98304
__global__ __launch_bounds__(256) void gates_kernel(const float* __restrict__ wi,
                                                    const float* __restrict__ bi,
                                                    const float* __restrict__ wf,
                                                    const float* __restrict__ bf)
{
    extern __shared__ __align__(16) float wsm[];   // [2][3072][4]
    int tid = threadIdx.x;
    // stage weights once (bit-exact fp32)
    float4* s4 = (float4*)wsm;
    const float4* wi4 = (const float4*)wi;
    const float4* wf4 = (const float4*)wf;
    #pragma unroll
    for (int i = tid; i < 3072; i += 256) {
        s4[i]        = wi4[i];
        s4[3072 + i] = wf4[i];
    }
    __syncthreads();

    int d = tid << 2;
    int lane = tid & 31, wid = tid >> 5;
    __shared__ float red[64];
    const float* wiq = wsm + (size_t)d * 4;
    const float* wfq = wsm + 12288 + (size_t)d * 4;

    #pragma unroll 1
    for (int rl = 0; rl < GROWS; rl++) {
        int row = blockIdx.x * GROWS + rl;
        const __half2* qh = (const __half2*)(g_qk16 + (size_t)row * 2048 + d);
        const __half2* kh = (const __half2*)(g_qk16 + (size_t)row * 2048 + 1024 + d);
        const __half2* vh = (const __half2*)(g_v16 + (size_t)row * II + d);
        float2 q01 = __half22float2(qh[0]), q23 = __half22float2(qh[1]);
        float2 k01 = __half22float2(kh[0]), k23 = __half22float2(kh[1]);
        float2 v01 = __half22float2(vh[0]), v23 = __half22float2(vh[1]);
        float qa[4] = {q01.x, q01.y, q23.x, q23.y};
        float ka[4] = {k01.x, k01.y, k23.x, k23.y};
        float va[4] = {v01.x, v01.y, v23.x, v23.y};
        float ai[HH] = {0,0,0,0}, af[HH] = {0,0,0,0};
        #pragma unroll
        for (int j = 0; j < 4; j++) {
            float aq = qa[j], ak = ka[j], av = va[j];
            const float* pq = wiq + j * 4;
            const float* pk = pq + 4096;      // (II + d + j)*4
            const float* pv = pq + 8192;      // (2*II + d + j)*4
            const float* fq = wfq + j * 4;
            const float* fk = fq + 4096;
            const float* fv = fq + 8192;
            #pragma unroll
            for (int h2 = 0; h2 < HH; h2++) {
                ai[h2] += aq * pq[h2] + ak * pk[h2] + av * pv[h2];
                af[h2] += aq * fq[h2] + ak * fk[h2] + av * fv[h2];
            }
        }
        #pragma unroll
        for (int s = 0; s < 8; s++) {
            float x = (s < 4) ? ai[s] : af[s-4];
            for (int o = 16; o; o >>= 1) x += __shfl_down_sync(0xffffffffu, x, o);
            if (lane == 0) red[s * 8 + wid] = x;
        }
        __syncthreads();
        if (tid < 64) {
            float x = red[tid];
            x += __shfl_down_sync(0xffffffffu, x, 4, 8);
            x += __shfl_down_sync(0xffffffffu, x, 2, 8);
            x += __shfl_down_sync(0xffffffffu, x, 1, 8);
            if ((tid & 7) == 0) {
                int s = tid >> 3;
                int b = row >> 10, t = row & (SS - 1);
                if (s < 4) g_ipre[((size_t)b*HH + s)     * SS + t] = x + bi[s];
                else       g_fpre[((size_t)b*HH + (s-4)) * SS + t] = x + bf[s-4];
            }
        }
        __syncthreads();
    }
}

// ---------------- gate scan (warp-shuffle): lfc, u, M, m ------------------------
__global__ __launch_bounds__(1024) void cumsum_kernel()
{
    int bh = blockIdx.x;
    int t  = threadIdx.x;
    int lane = t & 31, wd = t >> 5;
    float f  = g_fpre[bh * SS + t];
    float lf = (f > 0.f) ? -log1pf(__expf(-f)) : f - log1pf(__expf(f));

    float v = lf;
    #pragma unroll
    for (int o = 1; o < 32; o <<= 1) {
        float n = __shfl_up_sync(0xffffffffu, v, o);
        if (lane >= o) v += n;
    }
    __shared__ float ws[32], wm[32];
    if (lane == 31) ws[wd] = v;
    __syncthreads();
    if (wd == 0) {
        float w = ws[lane];
        #pragma unroll
        for (int o = 1; o < 32; o <<= 1) {
            float n = __shfl_up_sync(0xffffffffu, w, o);
            if (lane >= o) w += n;
        }
        ws[lane] = w;
    }
    __syncthreads();
    float lfc = v + (wd > 0 ? ws[wd - 1] : 0.f);
    float u = g_ipre[bh * SS + t] - lfc;
    g_u[bh * SS + t] = u;

    float m = u;
    #pragma unroll
    for (int o = 1; o < 32; o <<= 1) {
        float n = __shfl_up_sync(0xffffffffu, m, o);
        if (lane >= o) m = fmaxf(m, n);
    }
    if (lane == 31) wm[wd] = m;
    __syncthreads();
    if (wd == 0) {
        float w = wm[lane];
        #pragma unroll
        for (int o = 1; o < 32; o <<= 1) {
            float n = __shfl_up_sync(0xffffffffu, w, o);
            if (lane >= o) w = fmaxf(w, n);
        }
        wm[lane] = w;
    }
    __syncthreads();
    float M = (wd > 0) ? fmaxf(m, wm[wd - 1]) : m;
    g_mx[bh * SS + t] = M;
    g_mm[bh * SS + t] = lfc + M;
}

// ---------------- fp16 tensor-core causal mLSTM attention ----------------------
#define OFF_KS  32768
#define OFF_VS  65536
#define OFF_PS  98304
#define OFF_U   106496
#define OFF_SS  106752
#define ATT3_SMEM 107776

__global__ __launch_bounds__(256) void attn3_kernel(const __half* __restrict__ vT)
{
    extern __shared__ __align__(128) char sm2[];
    float* u_sh  = (float*)(sm2 + OFF_U);
    float* ss_sh = (float*)(sm2 + OFF_SS);
    uint32_t sb2 = smem_u32(sm2);

    int bh = blockIdx.x;
    int tb = (int)gridDim.y - 1 - (int)blockIdx.y;
    int b = bh >> 2, h = bh & 3;
    int tid = threadIdx.x;
    int wid = tid >> 5, lane = tid & 31;
    int laneR = lane >> 2, laneC = lane & 3;
    int warp_m = wid & 1, warp_n = wid >> 1;
    int t0 = tb * 64;
    size_t qkbase = ((size_t)b * SS) * 2048 + (size_t)h * DHH;
    size_t obase  = ((size_t)b * SS) * II + (size_t)h * DHH;
    const __half* vTb = vT + (size_t)bh * DHH * SS;

    #pragma unroll
    for (int j = 0; j < 8; j++) {
        int i = tid + 256 * j;
        int r = i >> 5, c = i & 31;
        cp_async16(sb2 + r * 512 + ((c ^ (r & 7)) << 4),
                   g_qk16 + qkbase + (size_t)(t0 + r) * 2048 + (c << 3));
    }
    CP_COMMIT();

    float Mr[4], ssum[4];
    #pragma unroll
    for (int k = 0; k < 4; k++) {
        int row = warp_m * 32 + (k >> 1) * 16 + (k & 1) * 8 + laneR;
        Mr[k] = g_mx[bh * SS + t0 + row];
        ssum[k] = 0.f;
    }

    float o[2][8][4];
    #pragma unroll
    for (int mf = 0; mf < 2; mf++)
        #pragma unroll
        for (int nf = 0; nf < 8; nf++)
            #pragma unroll
            for (int u = 0; u < 4; u++) o[mf][nf][u] = 0.f;

    int aRow = (lane & 15);
    int aSel = lane >> 4;
    int bRow = (lane & 7) | ((lane >> 1) & 8);
    int bSel = (lane >> 3) & 1;

    #pragma unroll 1
    for (int sb = 0; sb <= tb; sb++) {
        int s0 = sb * 64;
        __syncthreads();
        #pragma unroll
        for (int j = 0; j < 8; j++) {
            int i = tid + 256 * j;
            int r = i >> 5, c = i & 31;
            cp_async16(sb2 + OFF_KS + r * 512 + ((c ^ (r & 7)) << 4),
                       g_qk16 + qkbase + 1024 + (size_t)(s0 + r) * 2048 + (c << 3));
        }
        #pragma unroll
        for (int j = 0; j < 8; j++) {
            int i = tid + 256 * j;
            int r = i >> 3, c = i & 7;
            cp_async16(sb2 + OFF_VS + (r << 7) + ((c ^ (r & 7)) << 4),
                       vTb + (size_t)r * SS + s0 + (c << 3));
        }
        CP_COMMIT();
        if (tid < 16)
            *(float4*)(u_sh + tid * 4) = *(const float4*)(g_u + bh * SS + s0 + tid * 4);
        CP_WAIT0();
        __syncthreads();

        // ---- GEMM1: S = Q K^T ----
        float s8[2][2][4];
        #pragma unroll
        for (int mf = 0; mf < 2; mf++)
            #pragma unroll
            for (int nf = 0; nf < 2; nf++)
                #pragma unroll
                for (int u = 0; u < 4; u++) s8[mf][nf][u] = 0.f;
        {
            int ar = warp_m * 32 + aRow;
            uint32_t aBase0 = sb2 + ar * 512;
            uint32_t aBase1 = aBase0 + 16 * 512;
            uint32_t axr = (uint32_t)(ar & 7);
            int br = warp_n * 16 + bRow;
            uint32_t bBase = sb2 + OFF_KS + br * 512;
            uint32_t bxr = (uint32_t)(br & 7);
            #pragma unroll
            for (int ks = 0; ks < 16; ks++) {
                uint32_t ca = (uint32_t)(2 * ks + aSel) ^ axr;
                uint32_t cb = (uint32_t)(2 * ks + bSel) ^ bxr;
                uint32_t a0[4], a1[4], bq[4];
                LDSM_X4(a0, aBase0 + (ca << 4));
                LDSM_X4(a1, aBase1 + (ca << 4));
                LDSM_X4(bq, bBase + (cb << 4));
                mma_f16(s8[0][0], a0, bq[0], bq[1]);
                mma_f16(s8[0][1], a0, bq[2], bq[3]);
                mma_f16(s8[1][0], a1, bq[0], bq[1]);
                mma_f16(s8[1][1], a1, bq[2], bq[3]);
            }
        }

        // ---- weights + mask -> P (fp16) + running score sums ----
        bool diag = (sb == tb);
        #pragma unroll
        for (int mf = 0; mf < 2; mf++) {
            #pragma unroll
            for (int e = 0; e < 2; e++) {
                int row = warp_m * 32 + mf * 16 + e * 8 + laneR;
                int tg = t0 + row;
                float M = Mr[mf * 2 + e];
                #pragma unroll
                for (int nf = 0; nf < 2; nf++) {
                    int cb = warp_n * 16 + nf * 8 + 2 * laneC;
                    float d0 = s8[mf][nf][2 * e] * 0.0625f;
                    float d1 = s8[mf][nf][2 * e + 1] * 0.0625f;
                    float w0 = (!diag || (s0 + cb)     <= tg) ? __expf(u_sh[cb]     - M) : 0.f;
                    float w1 = (!diag || (s0 + cb + 1) <= tg) ? __expf(u_sh[cb + 1] - M) : 0.f;
                    __half2 pk = __floats2half2_rn(d0 * w0, d1 * w1);
                    ssum[mf * 2 + e] += __low2float(pk) + __high2float(pk);
                    *(__half2*)(sm2 + OFF_PS + (row << 7)
                                + (((cb >> 3) ^ (row & 7)) << 4) + ((cb & 7) << 1)) = pk;
                }
            }
        }
        __syncthreads();

        // ---- GEMM2: O += P Vs ----
        {
            int ar = warp_m * 32 + aRow;
            uint32_t aBase0 = sb2 + OFF_PS + (ar << 7);
            uint32_t aBase1 = aBase0 + (16 << 7);
            uint32_t axr = (uint32_t)(ar & 7);
            uint32_t bB[4], bxr[4];
            #pragma unroll
            for (int nf2 = 0; nf2 < 4; nf2++) {
                int br = warp_n * 64 + nf2 * 16 + bRow;
                bB[nf2] = sb2 + OFF_VS + (br << 7);
                bxr[nf2] = (uint32_t)(br & 7);
            }
            #pragma unroll
            for (int ks = 0; ks < 4; ks++) {
                uint32_t ca = ((uint32_t)(2 * ks + aSel) ^ axr) << 4;
                uint32_t a0[4], a1[4];
                LDSM_X4(a0, aBase0 + ca);
                LDSM_X4(a1, aBase1 + ca);
                #pragma unroll
                for (int nf2 = 0; nf2 < 4; nf2++) {
                    uint32_t cb = ((uint32_t)(2 * ks + bSel) ^ bxr[nf2]) << 4;
                    uint32_t bq[4];
                    LDSM_X4(bq, bB[nf2] + cb);
                    mma_f16(o[0][nf2 * 2],     a0, bq[0], bq[1]);
                    mma_f16(o[0][nf2 * 2 + 1], a0, bq[2], bq[3]);
                    mma_f16(o[1][nf2 * 2],     a1, bq[0], bq[1]);
                    mma_f16(o[1][nf2 * 2 + 1], a1, bq[2], bq[3]);
                }
            }
        }
    }

    // ---- epilogue ----
    #pragma unroll
    for (int k = 0; k < 4; k++) {
        ssum[k] += __shfl_xor_sync(0xffffffffu, ssum[k], 1);
        ssum[k] += __shfl_xor_sync(0xffffffffu, ssum[k], 2);
    }
    if (laneC == 0) {
        #pragma unroll
        for (int k = 0; k < 4; k++) {
            int row = warp_m * 32 + (k >> 1) * 16 + (k & 1) * 8 + laneR;
            ss_sh[warp_n * 64 + row] = ssum[k];
        }
    }
    __syncthreads();
    float inv[4];
    #pragma unroll
    for (int k = 0; k < 4; k++) {
        int row = warp_m * 32 + (k >> 1) * 16 + (k & 1) * 8 + laneR;
        float tot = ss_sh[row] + ss_sh[64 + row] + ss_sh[128 + row] + ss_sh[192 + row];
        float mm = g_mm[bh * SS + t0 + row];
        inv[k] = 1.f / fmaxf(fabsf(tot), __expf(-mm));
    }
    #pragma unroll
    for (int mf = 0; mf < 2; mf++) {
        int r0 = t0 + warp_m * 32 + mf * 16 + laneR;
        float i0 = inv[mf * 2], i1 = inv[mf * 2 + 1];
        #pragma unroll
        for (int nf = 0; nf < 8; nf++) {
            int c = warp_n * 64 + nf * 8 + 2 * laneC;
            *(float2*)(g_h + obase + (size_t)r0 * II + c) =
                make_float2(o[mf][nf][0] * i0, o[mf][nf][1] * i0);
            *(float2*)(g_h + obase + (size_t)(r0 + 8) * II + c) =
                make_float2(o[mf][nf][2] * i1, o[mf][nf][3] * i1);
        }
    }
}

// ---------------- per-head norm + gate, 1 sync, float4 (stores fp16) -----------
__global__ __launch_bounds__(256) void headgate_kernel(const float* __restrict__ gn,
                                                       const float* __restrict__ sk)
{
    int row = blockIdx.x;
    int tid = threadIdx.x;
    int wid = tid >> 5, lane = tid & 31;
    int h = wid >> 1;
    int c = h * DHH + (wid & 1) * 128 + lane * 4;
    size_t base = (size_t)row * II;
    float4 v = *(const float4*)(g_h + base + c);
    float s  = v.x + v.y + v.z + v.w;
    float s2 = v.x*v.x + v.y*v.y + v.z*v.z + v.w*v.w;
    for (int o = 16; o; o >>= 1) {
        s  += __shfl_down_sync(0xffffffffu, s,  o);
        s2 += __shfl_down_sync(0xffffffffu, s2, o);
    }
    __shared__ float sh[16];
    if (lane == 0) { sh[wid] = s; sh[8 + wid] = s2; }
    __syncthreads();
    float ts  = sh[h*2]     + sh[h*2 + 1];
    float ts2 = sh[8 + h*2] + sh[8 + h*2 + 1];
    float mu  = ts  * (1.f/DHH);
    float var = ts2 * (1.f/DHH) - mu*mu;
    float rstd = rsqrtf(var + EPS);
    float4 gn4 = *(const float4*)(gn + c);
    float4 sk4 = *(const float4*)(sk + c);
    float4 ca4 = *(const float4*)(g_cact + base + c);
    const __half2* zp = (const __half2*)(g_up16 + (size_t)row * 2048 + II + c);
    float2 z01 = __half22float2(zp[0]);
    float2 z23 = __half22float2(zp[1]);
    float zz[4] = {z01.x, z01.y, z23.x, z23.y};
    float hn[4];
    hn[0] = (v.x - mu) * rstd * gn4.x + sk4.x * ca4.x;
    hn[1] = (v.y - mu) * rstd * gn4.y + sk4.y * ca4.y;
    hn[2] = (v.z - mu) * rstd * gn4.z + sk4.z * ca4.z;
    hn[3] = (v.w - mu) * rstd * gn4.w + sk4.w * ca4.w;
    #pragma unroll
    for (int j = 0; j < 4; j++)
        hn[j] *= zz[j] / (1.f + __expf(-zz[j]));
    __half2* p = (__half2*)(g_h16 + base + c);
    p[0] = __floats2half2_rn(hn[0], hn[1]);
    p[1] = __floats2half2_rn(hn[2], hn[3]);
}

// ------------------------------- host -----------------------------------------
#define W16_UP(l)   (w16 + (size_t)(l)*1048576)
#define W16_QK(l)   (w16 + 2097152 + (size_t)(l)*2097152)
#define W16_V(l)    (w16 + 6291456 + (size_t)(l)*1048576)
#define W16_DOWN(l) (w16 + 8388608 + (size_t)(l)*524288)
#define W16_FIN     (w16 + 9437184)

static inline void launch_gemm(const __half* A, int lda, const __half* BT, int ldb,
                               float* C, int ldc, int M, int N, int K,
                               const float* bias, const float* res, int ldres,
                               __half* C2h = nullptr)
{
    dim3 grid(N / 128, M / 128);
    hgemm_kernel<<<grid, 256, GEMM_SMEM>>>(A, lda, BT, ldb, C, ldc, K,
                                           bias, res, ldres, C2h);
}

extern "C" void kernel_launch(void* const* d_in, const int* in_sizes, int n_in,
                              void* d_out, int out_size)
{
    (void)in_sizes; (void)n_in; (void)out_size;
    const float* x      = (const float*)d_in[0];
    const float* ln_g   = (const float*)d_in[1];
    const float* ln_b   = (const float*)d_in[2];
    const float* w_up   = (const float*)d_in[3];
    const float* conv_w = (const float*)d_in[4];
    const float* conv_b = (const float*)d_in[5];
    const float* wq     = (const float*)d_in[6];
    const float* wk     = (const float*)d_in[7];
    const float* wv     = (const float*)d_in[8];
    const float* w_i    = (const float*)d_in[9];
    const float* b_i    = (const float*)d_in[10];
    const float* w_f    = (const float*)d_in[11];
    const float* b_f    = (const float*)d_in[12];
    const float* skip   = (const float*)d_in[13];
    const float* gn_g   = (const float*)d_in[14];
    const float* w_down = (const float*)d_in[15];
    const float* b_down = (const float*)d_in[16];
    const float* w_fin  = (const float*)d_in[17];
    const float* b_fin  = (const float*)d_in[18];

    float *x1;
    __half *xn16, *up16, *ca16, *qk16, *h16, *x116, *w16, *vT, *v16;
    cudaGetSymbolAddress((void**)&xn16, g_xn16);
    cudaGetSymbolAddress((void**)&up16, g_up16);
    cudaGetSymbolAddress((void**)&ca16, g_ca16);
    cudaGetSymbolAddress((void**)&qk16, g_qk16);
    cudaGetSymbolAddress((void**)&h16,  g_h16);
    cudaGetSymbolAddress((void**)&x1,   g_x1);
    cudaGetSymbolAddress((void**)&x116, g_x116);
    cudaGetSymbolAddress((void**)&w16,  g_w16);
    cudaGetSymbolAddress((void**)&vT,   g_vT);
    cudaGetSymbolAddress((void**)&v16,  g_v16);

    cudaFuncSetAttribute(hgemm_kernel, cudaFuncAttributeMaxDynamicSharedMemorySize,
                         GEMM_SMEM);
    cudaFuncSetAttribute(attn3_kernel, cudaFuncAttributeMaxDynamicSharedMemorySize,
                         ATT3_SMEM);
    cudaFuncSetAttribute(gates_kernel, cudaFuncAttributeMaxDynamicSharedMemorySize,
                         GATES_SMEM);

    // weights -> fp16 transposed, single fused launch (q|k packed per layer)
    wtrans_all_kernel<<<9280, 256>>>(w_up, wq, wk, wv, w_down, w_fin, w16);

    const float* cur = x;
    for (int l = 0; l < 2; l++) {
        ln_kernel<<<BSR, 256>>>(cur, ln_g + l*EE, ln_b + l*EE, xn16);
        launch_gemm(xn16, EE, W16_UP(l), EE, nullptr, 2048, BSR, 2048, EE,
                    nullptr, nullptr, 0, up16);
        conv_silu_kernel<<<(BSR*II)/1024, 256>>>(conv_w + l*KKC*II, conv_b + l*II);
        launch_gemm(ca16, II, W16_QK(l), II, nullptr, 2048, BSR, 2048, II,
                    nullptr, nullptr, 0, qk16);
        launch_gemm(up16, 2048, W16_V(l), II, nullptr, II, BSR, II, II,
                    nullptr, nullptr, 0, v16);
        gates_kernel<<<BSR/GROWS, 256, GATES_SMEM>>>(
            w_i + (size_t)l*3*II*HH, b_i + l*HH,
            w_f + (size_t)l*3*II*HH, b_f + l*HH);
        cumsum_kernel<<<BB*HH, SS>>>();
        vtrans_kernel<<<dim3(SS/32, DHH/32, BB*HH), 256>>>(vT);
        attn3_kernel<<<dim3(BB*HH, SS/64), 256, ATT3_SMEM>>>(vT);
        headgate_kernel<<<BSR, 256>>>(gn_g + l*II, skip + l*II);
        launch_gemm(h16, II, W16_DOWN(l), II, x1, EE, BSR, EE, II,
                    b_down + l*EE, cur, EE, x116);
        cur = x1;
    }
    // final: (8192,512)@(512,128) + b_fin
    launch_gemm(x116, EE, W16_FIN, EE, (float*)d_out, 128, BSR, 128, EE,
                b_fin, nullptr, 0);
}

// round 16
// speedup vs baseline: 1.7410x; 1.7410x over previous
#include <cuda_runtime.h>
#include <cuda_fp16.h>
#include <cstdint>
#include <math.h>

// Problem dims
#define BB   8
#define SS   1024
#define EE   512
#define II   1024
#define HH   4
#define DHH  256
#define KKC  4
#define BSR  (BB*SS)          // 8192 rows
#define EPS  1e-5f

// ---------------- scratch (static device memory; rewritten every call) ----------
__device__ __half g_xn16[BSR*EE];         // fp16 LN out (up GEMM A)
__device__ __half g_up16[BSR*2048];       // fp16 up out: x_m cols [0,1024), z cols [1024,2048)
__device__ float g_cact[BSR*II];          // fp32 (headgate skip)
__device__ __half g_ca16[BSR*II];         // fp16 conv act (qk GEMM A)
__device__ __half g_qk16[BSR*2048];       // fp16 q|k (attn + gates), stride 2048
__device__ __half g_v16[BSR*II];          // fp16 v (vtrans + gates)
__device__ float g_h   [BSR*II];          // attn out (fp32)
__device__ __half g_h16[BSR*II];          // headgate out (down GEMM A)
__device__ float g_x1  [BSR*EE];          // fp32 residual stream
__device__ __half g_x116[BSR*EE];         // fp16 copy (fin GEMM A)
__device__ float g_ipre[BB*HH*SS];
__device__ float g_fpre[BB*HH*SS];
__device__ float g_u   [BB*HH*SS];
__device__ float g_mx  [BB*HH*SS];
__device__ float g_mm  [BB*HH*SS];
__device__ __half g_vT [32*256*1024];     // V^T per (b,h), fp16 (16MB)
__device__ __half g_w16[9502720];         // fp16 weights, transposed layouts

__device__ __forceinline__ uint32_t smem_u32(const void* p) {
    uint32_t a;
    asm("{ .reg .u64 t; cvta.to.shared.u64 t, %1; cvt.u32.u64 %0, t; }" : "=r"(a) : "l"(p));
    return a;
}
__device__ __forceinline__ void cp_async16(uint32_t dst, const void* src) {
    asm volatile("cp.async.cg.shared.global [%0], [%1], 16;" :: "r"(dst), "l"(src));
}
#define CP_COMMIT() asm volatile("cp.async.commit_group;" ::: "memory")
#define CP_WAIT1()  asm volatile("cp.async.wait_group 1;"  ::: "memory")
#define CP_WAIT0()  asm volatile("cp.async.wait_group 0;"  ::: "memory")

__device__ __forceinline__ void mma_f16(float* d, const uint32_t* a, uint32_t b0, uint32_t b1) {
    asm volatile("mma.sync.aligned.m16n8k16.row.col.f32.f16.f16.f32 "
        "{%0,%1,%2,%3}, {%4,%5,%6,%7}, {%8,%9}, {%0,%1,%2,%3};"
        : "+f"(d[0]), "+f"(d[1]), "+f"(d[2]), "+f"(d[3])
        : "r"(a[0]), "r"(a[1]), "r"(a[2]), "r"(a[3]), "r"(b0), "r"(b1));
}
#define LDSM_X4(r, addr) \
    asm volatile("ldmatrix.sync.aligned.m8n8.x4.shared.b16 {%0,%1,%2,%3}, [%4];" \
        : "=r"((r)[0]), "=r"((r)[1]), "=r"((r)[2]), "=r"((r)[3]) : "r"(addr))

// ================= fp16 mma.sync GEMM, cp.async 3-stage, ldmatrix ==============
__device__ __forceinline__ uint32_t sw_off(int r, int c) {
    return (uint32_t)(((r >> 1) << 7) + (((((r & 1) << 2) + c) ^ ((r >> 1) & 7)) << 4));
}

__device__ __forceinline__ void issue_tile16(uint32_t sA, uint32_t sB,
        const __half* A, int lda, const __half* BT, int ldb,
        int row0, int col0, int k0, int tid)
{
    const __half* Ag = A + (size_t)row0 * lda + k0;
    const __half* Bg = BT + (size_t)col0 * ldb + k0;
    #pragma unroll
    for (int j = 0; j < 2; j++) {
        int i = tid + 256 * j;
        int r = i >> 2, c = i & 3;
        cp_async16(sA + sw_off(r, c), Ag + (size_t)r * lda + (c << 3));
    }
    #pragma unroll
    for (int j = 0; j < 2; j++) {
        int i = tid + 256 * j;
        int r = i >> 2, c = i & 3;
        cp_async16(sB + sw_off(r, c), Bg + (size_t)r * ldb + (c << 3));
    }
}

__device__ __forceinline__ void compute_tile16(uint32_t sA, uint32_t sB,
        float d[4][4][4], int warp_m, int warp_n, int lane)
{
    int aRow = lane & 15, aCs = lane >> 4;
    int bRow = (lane & 7) | ((lane >> 1) & 8), bCs = (lane >> 3) & 1;
    uint32_t aBase = sA + (uint32_t)(warp_m * 4096) + sw_off(aRow, aCs);
    uint32_t bBase = sB + (uint32_t)(warp_n * 2048) + sw_off(bRow, bCs);
    #pragma unroll
    for (int ks = 0; ks < 2; ks++) {
        uint32_t kx = (uint32_t)(ks << 5);
        uint32_t a[4][4], b[2][4];
        #pragma unroll
        for (int mf = 0; mf < 4; mf++)
            LDSM_X4(a[mf], (aBase + mf * 1024) ^ kx);
        LDSM_X4(b[0], bBase ^ kx);
        LDSM_X4(b[1], (bBase + 1024) ^ kx);
        #pragma unroll
        for (int mf = 0; mf < 4; mf++) {
            mma_f16(d[mf][0], a[mf], b[0][0], b[0][1]);
            mma_f16(d[mf][1], a[mf], b[0][2], b[0][3]);
            mma_f16(d[mf][2], a[mf], b[1][0], b[1][1]);
            mma_f16(d[mf][3], a[mf], b[1][2], b[1][3]);
        }
    }
}

#define GEMM_SMEM (3 * 16384)

__global__ __launch_bounds__(256) void hgemm_kernel(
    const __half* __restrict__ A, int lda,
    const __half* __restrict__ BT, int ldb,   // [N,K]
    float* __restrict__ C, int ldc, int K,
    const float* __restrict__ bias,
    const float* __restrict__ res, int ldres,
    __half* __restrict__ C2h)
{
    extern __shared__ __align__(128) char sm[];
    uint32_t sbase = smem_u32(sm);

    int tid = threadIdx.x;
    int wid = tid >> 5, lane = tid & 31;
    int laneR = lane >> 2, laneC = lane & 3;
    int warp_m = wid & 1, warp_n = wid >> 1;
    int row0 = blockIdx.y * 128, col0 = blockIdx.x * 128;

    float d[4][4][4];
    #pragma unroll
    for (int i = 0; i < 4; i++)
        #pragma unroll
        for (int j = 0; j < 4; j++)
            #pragma unroll
            for (int u = 0; u < 4; u++) d[i][j][u] = 0.f;

    const int NK = K >> 5;

    issue_tile16(sbase, sbase + 8192, A, lda, BT, ldb, row0, col0, 0, tid);
    CP_COMMIT();
    issue_tile16(sbase + 16384, sbase + 24576, A, lda, BT, ldb, row0, col0, 32, tid);
    CP_COMMIT();

    #pragma unroll 1
    for (int kt = 0; kt < NK; kt++) {
        CP_WAIT1();
        __syncthreads();
        if (kt + 2 < NK) {
            uint32_t s = (uint32_t)((kt + 2) % 3) * 16384;
            issue_tile16(sbase + s, sbase + s + 8192,
                         A, lda, BT, ldb, row0, col0, (kt + 2) << 5, tid);
        }
        CP_COMMIT();
        uint32_t b = (uint32_t)(kt % 3) * 16384;
        compute_tile16(sbase + b, sbase + b + 8192, d, warp_m, warp_n, lane);
    }

    #pragma unroll
    for (int mf = 0; mf < 4; mf++) {
        int r = row0 + warp_m * 64 + mf * 16 + laneR;
        #pragma unroll
        for (int nf = 0; nf < 4; nf++) {
            int cc = col0 + warp_n * 32 + nf * 8 + 2 * laneC;
            float2 v0 = make_float2(d[mf][nf][0], d[mf][nf][1]);
            float2 v1 = make_float2(d[mf][nf][2], d[mf][nf][3]);
            if (bias) {
                float2 bv = *(const float2*)(bias + cc);
                v0.x += bv.x; v0.y += bv.y;
                v1.x += bv.x; v1.y += bv.y;
            }
            if (res) {
                float2 r0 = *(const float2*)(res + (size_t)r * ldres + cc);
                float2 r1 = *(const float2*)(res + (size_t)(r + 8) * ldres + cc);
                v0.x += r0.x; v0.y += r0.y;
                v1.x += r1.x; v1.y += r1.y;
            }
            if (C) {
                *(float2*)(C + (size_t)r * ldc + cc)       = v0;
                *(float2*)(C + (size_t)(r + 8) * ldc + cc) = v1;
            }
            if (C2h) {
                *(__half2*)(C2h + (size_t)r * ldc + cc)       = __floats2half2_rn(v0.x, v0.y);
                *(__half2*)(C2h + (size_t)(r + 8) * ldc + cc) = __floats2half2_rn(v1.x, v1.y);
            }
        }
    }
}

// ---------------- fused weight transpose+convert ------------------------------
__global__ __launch_bounds__(256) void wtrans_all_kernel(
    const float* __restrict__ w_up, const float* __restrict__ wq,
    const float* __restrict__ wk,  const float* __restrict__ wv,
    const float* __restrict__ w_down, const float* __restrict__ w_fin,
    __half* __restrict__ w16)
{
    int bid = blockIdx.x;
    const float* in; __half* out; int K, N, loc;
    if (bid < 9216) {
        int l = bid / 4608, r = bid % 4608;
        if (r < 1024)      { in = w_up   + (size_t)l*1048576; out = w16 + (size_t)l*1048576;                     K = 512;  N = 2048; loc = r; }
        else if (r < 2048) { in = wq     + (size_t)l*1048576; out = w16 + 2097152 + (size_t)l*2097152;           K = 1024; N = 1024; loc = r - 1024; }
        else if (r < 3072) { in = wk     + (size_t)l*1048576; out = w16 + 2097152 + (size_t)l*2097152 + 1048576; K = 1024; N = 1024; loc = r - 2048; }
        else if (r < 4096) { in = wv     + (size_t)l*1048576; out = w16 + 6291456 + (size_t)l*1048576;           K = 1024; N = 1024; loc = r - 3072; }
        else               { in = w_down + (size_t)l*524288;  out = w16 + 8388608 + (size_t)l*524288;            K = 1024; N = 512;  loc = r - 4096; }
    } else {
        in = w_fin; out = w16 + 9437184; K = 512; N = 128; loc = bid - 9216;
    }
    int nw = N >> 5;
    int nb = (loc % nw) * 32, kb = (loc / nw) * 32;
    __shared__ float t[32][33];
    int tx = threadIdx.x & 31, ty = threadIdx.x >> 5;
    #pragma unroll
    for (int j = 0; j < 32; j += 8)
        t[ty + j][tx] = in[(size_t)(kb + ty + j) * N + nb + tx];
    __syncthreads();
    #pragma unroll
    for (int j = 0; j < 32; j += 8)
        out[(size_t)(nb + ty + j) * K + kb + tx] = __float2half_rn(t[tx][ty + j]);
}

// ---------------- V transpose per (b,h): g_v16 -> g_vT[bh][d][t], fp16 ---------
__global__ __launch_bounds__(256) void vtrans_kernel(__half* __restrict__ vT)
{
    __shared__ __half t[32][36];
    int bh = blockIdx.z;
    int b = bh >> 2, h = bh & 3;
    int t0 = blockIdx.x * 32, d0 = blockIdx.y * 32;
    int tx = threadIdx.x & 31, ty = threadIdx.x >> 5;
    #pragma unroll
    for (int j = 0; j < 32; j += 8)
        t[ty + j][tx] = g_v16[(size_t)(b * SS + t0 + ty + j) * II + h * DHH + d0 + tx];
    __syncthreads();
    #pragma unroll
    for (int j = 0; j < 32; j += 8)
        vT[((size_t)bh * DHH + d0 + ty + j) * SS + t0 + tx] = t[tx][ty + j];
}

// ---------------- LayerNorm over E=512 (stores fp16) ---------------------------
__global__ __launch_bounds__(256) void ln_kernel(const float* __restrict__ x,
                                                 const float* __restrict__ g,
                                                 const float* __restrict__ b,
                                                 __half* __restrict__ y)
{
    int row = blockIdx.x;
    const float* xr = x + (size_t)row * EE;
    int c2 = threadIdx.x * 2;
    float2 xv = *(const float2*)(xr + c2);
    float s = xv.x + xv.y, s2 = xv.x*xv.x + xv.y*xv.y;
    __shared__ float sh[64];
    for (int o = 16; o; o >>= 1) {
        s  += __shfl_down_sync(0xffffffffu, s,  o);
        s2 += __shfl_down_sync(0xffffffffu, s2, o);
    }
    int wid = threadIdx.x >> 5, lane = threadIdx.x & 31;
    if (lane == 0) { sh[wid] = s; sh[32+wid] = s2; }
    __syncthreads();
    if (threadIdx.x == 0) {
        float ts = 0.f, ts2 = 0.f;
        for (int w = 0; w < 8; w++) { ts += sh[w]; ts2 += sh[32+w]; }
        sh[0] = ts; sh[32] = ts2;
    }
    __syncthreads();
    float mu  = sh[0]  * (1.f/EE);
    float var = sh[32] * (1.f/EE) - mu*mu;
    float rstd = rsqrtf(var + EPS);
    float2 gv = *(const float2*)(g + c2);
    float2 bv = *(const float2*)(b + c2);
    *(__half2*)(y + (size_t)row * EE + c2) =
        __floats2half2_rn((xv.x - mu) * rstd * gv.x + bv.x,
                          (xv.y - mu) * rstd * gv.y + bv.y);
}

// ---------------- causal depthwise conv (K=4) + SiLU, fp16 in, 4 ch/thread -----
__global__ __launch_bounds__(256) void conv_silu_kernel(const float* __restrict__ cw,
                                                        const float* __restrict__ cb)
{
    int idx = blockIdx.x * 256 + threadIdx.x;
    int c4  = (idx & 255) << 2;
    int row = idx >> 8;
    int t   = row & (SS - 1);
    const __half* base = g_up16 + (size_t)row * 2048 + c4;
    float4 acc = *(const float4*)(cb + c4);
    #pragma unroll
    for (int j = 0; j < KKC; j++) {
        int tt = t - (KKC - 1) + j;
        if (tt >= 0) {
            const __half2* xp = (const __half2*)(base + (j - (KKC - 1)) * 2048);
            float2 x01 = __half22float2(xp[0]);
            float2 x23 = __half22float2(xp[1]);
            float4 wv = *(const float4*)(cw + j * II + c4);
            acc.x = fmaf(x01.x, wv.x, acc.x);
            acc.y = fmaf(x01.y, wv.y, acc.y);
            acc.z = fmaf(x23.x, wv.z, acc.z);
            acc.w = fmaf(x23.y, wv.w, acc.w);
        }
    }
    float4 sv;
    sv.x = acc.x / (1.f + __expf(-acc.x));
    sv.y = acc.y / (1.f + __expf(-acc.y));
    sv.z = acc.z / (1.f + __expf(-acc.z));
    sv.w = acc.w / (1.f + __expf(-acc.w));
    size_t o = (size_t)row * II + c4;
    *(float4*)(g_cact + o) = sv;
    __half2* p = (__half2*)(g_ca16 + o);
    p[0] = __floats2half2_rn(sv.x, sv.y);
    p[1] = __floats2half2_rn(sv.z, sv.w);
}

// ---------------- gate projections: 16 rows/block, transposed smem weights -----
// smem layout: wsm[g][dIdx], g in [0,8) = {ai0..3, af0..3}, dIdx in [0,3072).
// Per-thread float4 loads hit consecutive float4 slots across the warp -> no
// bank conflicts (this was the R15 bug: row-major staging gave 16-way conflicts).
#define GROWS 16
#define GATES_SMEM 98304
__global__ __launch_bounds__(256) void gates_kernel(const float* __restrict__ wi,
                                                    const float* __restrict__ bi,
                                                    const float* __restrict__ wf,
                                                    const float* __restrict__ bf)
{
    extern __shared__ __align__(16) float wsm[];   // [8][3072]
    int tid = threadIdx.x;
    // stage transposed: wsm[h][i] = wi[i][h], wsm[4+h][i] = wf[i][h]
    const float4* wi4 = (const float4*)wi;
    const float4* wf4 = (const float4*)wf;
    for (int i = tid; i < 3072; i += 256) {
        float4 a = wi4[i];
        wsm[i]           = a.x;
        wsm[3072 + i]    = a.y;
        wsm[6144 + i]    = a.z;
        wsm[9216 + i]    = a.w;
        float4 f = wf4[i];
        wsm[12288 + i]   = f.x;
        wsm[15360 + i]   = f.y;
        wsm[18432 + i]   = f.z;
        wsm[21504 + i]   = f.w;
    }
    __syncthreads();

    int d = tid << 2;
    int lane = tid & 31, wid = tid >> 5;
    __shared__ float red[64];

    #pragma unroll 1
    for (int rl = 0; rl < GROWS; rl++) {
        int row = blockIdx.x * GROWS + rl;
        const __half2* qh = (const __half2*)(g_qk16 + (size_t)row * 2048 + d);
        const __half2* kh = (const __half2*)(g_qk16 + (size_t)row * 2048 + 1024 + d);
        const __half2* vh = (const __half2*)(g_v16 + (size_t)row * II + d);
        float2 q01 = __half22float2(qh[0]), q23 = __half22float2(qh[1]);
        float2 k01 = __half22float2(kh[0]), k23 = __half22float2(kh[1]);
        float2 v01 = __half22float2(vh[0]), v23 = __half22float2(vh[1]);
        float qa[4] = {q01.x, q01.y, q23.x, q23.y};
        float ka[4] = {k01.x, k01.y, k23.x, k23.y};
        float va[4] = {v01.x, v01.y, v23.x, v23.y};
        float acc[8];
        #pragma unroll
        for (int g = 0; g < 8; g++) {
            const float* wg = wsm + g * 3072;
            float4 wq = *(const float4*)(wg + d);
            float4 wk = *(const float4*)(wg + 1024 + d);
            float4 wv = *(const float4*)(wg + 2048 + d);
            float x;
            x  = qa[0]*wq.x + qa[1]*wq.y + qa[2]*wq.z + qa[3]*wq.w;
            x += ka[0]*wk.x + ka[1]*wk.y + ka[2]*wk.z + ka[3]*wk.w;
            x += va[0]*wv.x + va[1]*wv.y + va[2]*wv.z + va[3]*wv.w;
            acc[g] = x;
        }
        #pragma unroll
        for (int s = 0; s < 8; s++) {
            float x = acc[s];
            for (int o = 16; o; o >>= 1) x += __shfl_down_sync(0xffffffffu, x, o);
            if (lane == 0) red[s * 8 + wid] = x;
        }
        __syncthreads();
        if (tid < 64) {
            float x = red[tid];
            x += __shfl_down_sync(0xffffffffu, x, 4, 8);
            x += __shfl_down_sync(0xffffffffu, x, 2, 8);
            x += __shfl_down_sync(0xffffffffu, x, 1, 8);
            if ((tid & 7) == 0) {
                int s = tid >> 3;
                int b = row >> 10, t = row & (SS - 1);
                if (s < 4) g_ipre[((size_t)b*HH + s)     * SS + t] = x + bi[s];
                else       g_fpre[((size_t)b*HH + (s-4)) * SS + t] = x + bf[s-4];
            }
        }
        __syncthreads();
    }
}

// ---------------- gate scan (warp-shuffle): lfc, u, M, m ------------------------
__global__ __launch_bounds__(1024) void cumsum_kernel()
{
    int bh = blockIdx.x;
    int t  = threadIdx.x;
    int lane = t & 31, wd = t >> 5;
    float f  = g_fpre[bh * SS + t];
    float lf = (f > 0.f) ? -log1pf(__expf(-f)) : f - log1pf(__expf(f));

    float v = lf;
    #pragma unroll
    for (int o = 1; o < 32; o <<= 1) {
        float n = __shfl_up_sync(0xffffffffu, v, o);
        if (lane >= o) v += n;
    }
    __shared__ float ws[32], wm[32];
    if (lane == 31) ws[wd] = v;
    __syncthreads();
    if (wd == 0) {
        float w = ws[lane];
        #pragma unroll
        for (int o = 1; o < 32; o <<= 1) {
            float n = __shfl_up_sync(0xffffffffu, w, o);
            if (lane >= o) w += n;
        }
        ws[lane] = w;
    }
    __syncthreads();
    float lfc = v + (wd > 0 ? ws[wd - 1] : 0.f);
    float u = g_ipre[bh * SS + t] - lfc;
    g_u[bh * SS + t] = u;

    float m = u;
    #pragma unroll
    for (int o = 1; o < 32; o <<= 1) {
        float n = __shfl_up_sync(0xffffffffu, m, o);
        if (lane >= o) m = fmaxf(m, n);
    }
    if (lane == 31) wm[wd] = m;
    __syncthreads();
    if (wd == 0) {
        float w = wm[lane];
        #pragma unroll
        for (int o = 1; o < 32; o <<= 1) {
            float n = __shfl_up_sync(0xffffffffu, w, o);
            if (lane >= o) w = fmaxf(w, n);
        }
        wm[lane] = w;
    }
    __syncthreads();
    float M = (wd > 0) ? fmaxf(m, wm[wd - 1]) : m;
    g_mx[bh * SS + t] = M;
    g_mm[bh * SS + t] = lfc + M;
}

// ---------------- fp16 tensor-core causal mLSTM attention ----------------------
#define OFF_KS  32768
#define OFF_VS  65536
#define OFF_PS  98304
#define OFF_U   106496
#define OFF_SS  106752
#define ATT3_SMEM 107776

__global__ __launch_bounds__(256) void attn3_kernel(const __half* __restrict__ vT)
{
    extern __shared__ __align__(128) char sm2[];
    float* u_sh  = (float*)(sm2 + OFF_U);
    float* ss_sh = (float*)(sm2 + OFF_SS);
    uint32_t sb2 = smem_u32(sm2);

    int bh = blockIdx.x;
    int tb = (int)gridDim.y - 1 - (int)blockIdx.y;
    int b = bh >> 2, h = bh & 3;
    int tid = threadIdx.x;
    int wid = tid >> 5, lane = tid & 31;
    int laneR = lane >> 2, laneC = lane & 3;
    int warp_m = wid & 1, warp_n = wid >> 1;
    int t0 = tb * 64;
    size_t qkbase = ((size_t)b * SS) * 2048 + (size_t)h * DHH;
    size_t obase  = ((size_t)b * SS) * II + (size_t)h * DHH;
    const __half* vTb = vT + (size_t)bh * DHH * SS;

    #pragma unroll
    for (int j = 0; j < 8; j++) {
        int i = tid + 256 * j;
        int r = i >> 5, c = i & 31;
        cp_async16(sb2 + r * 512 + ((c ^ (r & 7)) << 4),
                   g_qk16 + qkbase + (size_t)(t0 + r) * 2048 + (c << 3));
    }
    CP_COMMIT();

    float Mr[4], ssum[4];
    #pragma unroll
    for (int k = 0; k < 4; k++) {
        int row = warp_m * 32 + (k >> 1) * 16 + (k & 1) * 8 + laneR;
        Mr[k] = g_mx[bh * SS + t0 + row];
        ssum[k] = 0.f;
    }

    float o[2][8][4];
    #pragma unroll
    for (int mf = 0; mf < 2; mf++)
        #pragma unroll
        for (int nf = 0; nf < 8; nf++)
            #pragma unroll
            for (int u = 0; u < 4; u++) o[mf][nf][u] = 0.f;

    int aRow = (lane & 15);
    int aSel = lane >> 4;
    int bRow = (lane & 7) | ((lane >> 1) & 8);
    int bSel = (lane >> 3) & 1;

    #pragma unroll 1
    for (int sb = 0; sb <= tb; sb++) {
        int s0 = sb * 64;
        __syncthreads();
        #pragma unroll
        for (int j = 0; j < 8; j++) {
            int i = tid + 256 * j;
            int r = i >> 5, c = i & 31;
            cp_async16(sb2 + OFF_KS + r * 512 + ((c ^ (r & 7)) << 4),
                       g_qk16 + qkbase + 1024 + (size_t)(s0 + r) * 2048 + (c << 3));
        }
        #pragma unroll
        for (int j = 0; j < 8; j++) {
            int i = tid + 256 * j;
            int r = i >> 3, c = i & 7;
            cp_async16(sb2 + OFF_VS + (r << 7) + ((c ^ (r & 7)) << 4),
                       vTb + (size_t)r * SS + s0 + (c << 3));
        }
        CP_COMMIT();
        if (tid < 16)
            *(float4*)(u_sh + tid * 4) = *(const float4*)(g_u + bh * SS + s0 + tid * 4);
        CP_WAIT0();
        __syncthreads();

        // ---- GEMM1: S = Q K^T ----
        float s8[2][2][4];
        #pragma unroll
        for (int mf = 0; mf < 2; mf++)
            #pragma unroll
            for (int nf = 0; nf < 2; nf++)
                #pragma unroll
                for (int u = 0; u < 4; u++) s8[mf][nf][u] = 0.f;
        {
            int ar = warp_m * 32 + aRow;
            uint32_t aBase0 = sb2 + ar * 512;
            uint32_t aBase1 = aBase0 + 16 * 512;
            uint32_t axr = (uint32_t)(ar & 7);
            int br = warp_n * 16 + bRow;
            uint32_t bBase = sb2 + OFF_KS + br * 512;
            uint32_t bxr = (uint32_t)(br & 7);
            #pragma unroll
            for (int ks = 0; ks < 16; ks++) {
                uint32_t ca = (uint32_t)(2 * ks + aSel) ^ axr;
                uint32_t cb = (uint32_t)(2 * ks + bSel) ^ bxr;
                uint32_t a0[4], a1[4], bq[4];
                LDSM_X4(a0, aBase0 + (ca << 4));
                LDSM_X4(a1, aBase1 + (ca << 4));
                LDSM_X4(bq, bBase + (cb << 4));
                mma_f16(s8[0][0], a0, bq[0], bq[1]);
                mma_f16(s8[0][1], a0, bq[2], bq[3]);
                mma_f16(s8[1][0], a1, bq[0], bq[1]);
                mma_f16(s8[1][1], a1, bq[2], bq[3]);
            }
        }

        // ---- weights + mask -> P (fp16) + running score sums ----
        bool diag = (sb == tb);
        #pragma unroll
        for (int mf = 0; mf < 2; mf++) {
            #pragma unroll
            for (int e = 0; e < 2; e++) {
                int row = warp_m * 32 + mf * 16 + e * 8 + laneR;
                int tg = t0 + row;
                float M = Mr[mf * 2 + e];
                #pragma unroll
                for (int nf = 0; nf < 2; nf++) {
                    int cb = warp_n * 16 + nf * 8 + 2 * laneC;
                    float d0 = s8[mf][nf][2 * e] * 0.0625f;
                    float d1 = s8[mf][nf][2 * e + 1] * 0.0625f;
                    float w0 = (!diag || (s0 + cb)     <= tg) ? __expf(u_sh[cb]     - M) : 0.f;
                    float w1 = (!diag || (s0 + cb + 1) <= tg) ? __expf(u_sh[cb + 1] - M) : 0.f;
                    __half2 pk = __floats2half2_rn(d0 * w0, d1 * w1);
                    ssum[mf * 2 + e] += __low2float(pk) + __high2float(pk);
                    *(__half2*)(sm2 + OFF_PS + (row << 7)
                                + (((cb >> 3) ^ (row & 7)) << 4) + ((cb & 7) << 1)) = pk;
                }
            }
        }
        __syncthreads();

        // ---- GEMM2: O += P Vs ----
        {
            int ar = warp_m * 32 + aRow;
            uint32_t aBase0 = sb2 + OFF_PS + (ar << 7);
            uint32_t aBase1 = aBase0 + (16 << 7);
            uint32_t axr = (uint32_t)(ar & 7);
            uint32_t bB[4], bxr[4];
            #pragma unroll
            for (int nf2 = 0; nf2 < 4; nf2++) {
                int br = warp_n * 64 + nf2 * 16 + bRow;
                bB[nf2] = sb2 + OFF_VS + (br << 7);
                bxr[nf2] = (uint32_t)(br & 7);
            }
            #pragma unroll
            for (int ks = 0; ks < 4; ks++) {
                uint32_t ca = ((uint32_t)(2 * ks + aSel) ^ axr) << 4;
                uint32_t a0[4], a1[4];
                LDSM_X4(a0, aBase0 + ca);
                LDSM_X4(a1, aBase1 + ca);
                #pragma unroll
                for (int nf2 = 0; nf2 < 4; nf2++) {
                    uint32_t cb = ((uint32_t)(2 * ks + bSel) ^ bxr[nf2]) << 4;
                    uint32_t bq[4];
                    LDSM_X4(bq, bB[nf2] + cb);
                    mma_f16(o[0][nf2 * 2],     a0, bq[0], bq[1]);
                    mma_f16(o[0][nf2 * 2 + 1], a0, bq[2], bq[3]);
                    mma_f16(o[1][nf2 * 2],     a1, bq[0], bq[1]);
                    mma_f16(o[1][nf2 * 2 + 1], a1, bq[2], bq[3]);
                }
            }
        }
    }

    // ---- epilogue ----
    #pragma unroll
    for (int k = 0; k < 4; k++) {
        ssum[k] += __shfl_xor_sync(0xffffffffu, ssum[k], 1);
        ssum[k] += __shfl_xor_sync(0xffffffffu, ssum[k], 2);
    }
    if (laneC == 0) {
        #pragma unroll
        for (int k = 0; k < 4; k++) {
            int row = warp_m * 32 + (k >> 1) * 16 + (k & 1) * 8 + laneR;
            ss_sh[warp_n * 64 + row] = ssum[k];
        }
    }
    __syncthreads();
    float inv[4];
    #pragma unroll
    for (int k = 0; k < 4; k++) {
        int row = warp_m * 32 + (k >> 1) * 16 + (k & 1) * 8 + laneR;
        float tot = ss_sh[row] + ss_sh[64 + row] + ss_sh[128 + row] + ss_sh[192 + row];
        float mm = g_mm[bh * SS + t0 + row];
        inv[k] = 1.f / fmaxf(fabsf(tot), __expf(-mm));
    }
    #pragma unroll
    for (int mf = 0; mf < 2; mf++) {
        int r0 = t0 + warp_m * 32 + mf * 16 + laneR;
        float i0 = inv[mf * 2], i1 = inv[mf * 2 + 1];
        #pragma unroll
        for (int nf = 0; nf < 8; nf++) {
            int c = warp_n * 64 + nf * 8 + 2 * laneC;
            *(float2*)(g_h + obase + (size_t)r0 * II + c) =
                make_float2(o[mf][nf][0] * i0, o[mf][nf][1] * i0);
            *(float2*)(g_h + obase + (size_t)(r0 + 8) * II + c) =
                make_float2(o[mf][nf][2] * i1, o[mf][nf][3] * i1);
        }
    }
}

// ---------------- per-head norm + gate, 1 sync, float4 (stores fp16) -----------
__global__ __launch_bounds__(256) void headgate_kernel(const float* __restrict__ gn,
                                                       const float* __restrict__ sk)
{
    int row = blockIdx.x;
    int tid = threadIdx.x;
    int wid = tid >> 5, lane = tid & 31;
    int h = wid >> 1;
    int c = h * DHH + (wid & 1) * 128 + lane * 4;
    size_t base = (size_t)row * II;
    float4 v = *(const float4*)(g_h + base + c);
    float s  = v.x + v.y + v.z + v.w;
    float s2 = v.x*v.x + v.y*v.y + v.z*v.z + v.w*v.w;
    for (int o = 16; o; o >>= 1) {
        s  += __shfl_down_sync(0xffffffffu, s,  o);
        s2 += __shfl_down_sync(0xffffffffu, s2, o);
    }
    __shared__ float sh[16];
    if (lane == 0) { sh[wid] = s; sh[8 + wid] = s2; }
    __syncthreads();
    float ts  = sh[h*2]     + sh[h*2 + 1];
    float ts2 = sh[8 + h*2] + sh[8 + h*2 + 1];
    float mu  = ts  * (1.f/DHH);
    float var = ts2 * (1.f/DHH) - mu*mu;
    float rstd = rsqrtf(var + EPS);
    float4 gn4 = *(const float4*)(gn + c);
    float4 sk4 = *(const float4*)(sk + c);
    float4 ca4 = *(const float4*)(g_cact + base + c);
    const __half2* zp = (const __half2*)(g_up16 + (size_t)row * 2048 + II + c);
    float2 z01 = __half22float2(zp[0]);
    float2 z23 = __half22float2(zp[1]);
    float zz[4] = {z01.x, z01.y, z23.x, z23.y};
    float hn[4];
    hn[0] = (v.x - mu) * rstd * gn4.x + sk4.x * ca4.x;
    hn[1] = (v.y - mu) * rstd * gn4.y + sk4.y * ca4.y;
    hn[2] = (v.z - mu) * rstd * gn4.z + sk4.z * ca4.z;
    hn[3] = (v.w - mu) * rstd * gn4.w + sk4.w * ca4.w;
    #pragma unroll
    for (int j = 0; j < 4; j++)
        hn[j] *= zz[j] / (1.f + __expf(-zz[j]));
    __half2* p = (__half2*)(g_h16 + base + c);
    p[0] = __floats2half2_rn(hn[0], hn[1]);
    p[1] = __floats2half2_rn(hn[2], hn[3]);
}

// ------------------------------- host -----------------------------------------
#define W16_UP(l)   (w16 + (size_t)(l)*1048576)
#define W16_QK(l)   (w16 + 2097152 + (size_t)(l)*2097152)
#define W16_V(l)    (w16 + 6291456 + (size_t)(l)*1048576)
#define W16_DOWN(l) (w16 + 8388608 + (size_t)(l)*524288)
#define W16_FIN     (w16 + 9437184)

static inline void launch_gemm(const __half* A, int lda, const __half* BT, int ldb,
                               float* C, int ldc, int M, int N, int K,
                               const float* bias, const float* res, int ldres,
                               __half* C2h = nullptr)
{
    dim3 grid(N / 128, M / 128);
    hgemm_kernel<<<grid, 256, GEMM_SMEM>>>(A, lda, BT, ldb, C, ldc, K,
                                           bias, res, ldres, C2h);
}

extern "C" void kernel_launch(void* const* d_in, const int* in_sizes, int n_in,
                              void* d_out, int out_size)
{
    (void)in_sizes; (void)n_in; (void)out_size;
    const float* x      = (const float*)d_in[0];
    const float* ln_g   = (const float*)d_in[1];
    const float* ln_b   = (const float*)d_in[2];
    const float* w_up   = (const float*)d_in[3];
    const float* conv_w = (const float*)d_in[4];
    const float* conv_b = (const float*)d_in[5];
    const float* wq     = (const float*)d_in[6];
    const float* wk     = (const float*)d_in[7];
    const float* wv     = (const float*)d_in[8];
    const float* w_i    = (const float*)d_in[9];
    const float* b_i    = (const float*)d_in[10];
    const float* w_f    = (const float*)d_in[11];
    const float* b_f    = (const float*)d_in[12];
    const float* skip   = (const float*)d_in[13];
    const float* gn_g   = (const float*)d_in[14];
    const float* w_down = (const float*)d_in[15];
    const float* b_down = (const float*)d_in[16];
    const float* w_fin  = (const float*)d_in[17];
    const float* b_fin  = (const float*)d_in[18];

    float *x1;
    __half *xn16, *up16, *ca16, *qk16, *h16, *x116, *w16, *vT, *v16;
    cudaGetSymbolAddress((void**)&xn16, g_xn16);
    cudaGetSymbolAddress((void**)&up16, g_up16);
    cudaGetSymbolAddress((void**)&ca16, g_ca16);
    cudaGetSymbolAddress((void**)&qk16, g_qk16);
    cudaGetSymbolAddress((void**)&h16,  g_h16);
    cudaGetSymbolAddress((void**)&x1,   g_x1);
    cudaGetSymbolAddress((void**)&x116, g_x116);
    cudaGetSymbolAddress((void**)&w16,  g_w16);
    cudaGetSymbolAddress((void**)&vT,   g_vT);
    cudaGetSymbolAddress((void**)&v16,  g_v16);

    cudaFuncSetAttribute(hgemm_kernel, cudaFuncAttributeMaxDynamicSharedMemorySize,
                         GEMM_SMEM);
    cudaFuncSetAttribute(attn3_kernel, cudaFuncAttributeMaxDynamicSharedMemorySize,
                         ATT3_SMEM);
    cudaFuncSetAttribute(gates_kernel, cudaFuncAttributeMaxDynamicSharedMemorySize,
                         GATES_SMEM);

    // weights -> fp16 transposed, single fused launch (q|k packed per layer)
    wtrans_all_kernel<<<9280, 256>>>(w_up, wq, wk, wv, w_down, w_fin, w16);

    const float* cur = x;
    for (int l = 0; l < 2; l++) {
        ln_kernel<<<BSR, 256>>>(cur, ln_g + l*EE, ln_b + l*EE, xn16);
        launch_gemm(xn16, EE, W16_UP(l), EE, nullptr, 2048, BSR, 2048, EE,
                    nullptr, nullptr, 0, up16);
        conv_silu_kernel<<<(BSR*II)/1024, 256>>>(conv_w + l*KKC*II, conv_b + l*II);
        launch_gemm(ca16, II, W16_QK(l), II, nullptr, 2048, BSR, 2048, II,
                    nullptr, nullptr, 0, qk16);
        launch_gemm(up16, 2048, W16_V(l), II, nullptr, II, BSR, II, II,
                    nullptr, nullptr, 0, v16);
        gates_kernel<<<BSR/GROWS, 256, GATES_SMEM>>>(
            w_i + (size_t)l*3*II*HH, b_i + l*HH,
            w_f + (size_t)l*3*II*HH, b_f + l*HH);
        cumsum_kernel<<<BB*HH, SS>>>();
        vtrans_kernel<<<dim3(SS/32, DHH/32, BB*HH), 256>>>(vT);
        attn3_kernel<<<dim3(BB*HH, SS/64), 256, ATT3_SMEM>>>(vT);
        headgate_kernel<<<BSR, 256>>>(gn_g + l*II, skip + l*II);
        launch_gemm(h16, II, W16_DOWN(l), II, x1, EE, BSR, EE, II,
                    b_down + l*EE, cur, EE, x116);
        cur = x1;
    }
    // final: (8192,512)@(512,128) + b_fin
    launch_gemm(x116, EE, W16_FIN, EE, (float*)d_out, 128, BSR, 128, EE,
                b_fin, nullptr, 0);
}

// round 17
// speedup vs baseline: 1.7567x; 1.0090x over previous
#include <cuda_runtime.h>
#include <cuda_fp16.h>
#include <cstdint>
#include <math.h>

// Problem dims
#define BB   8
#define SS   1024
#define EE   512
#define II   1024
#define HH   4
#define DHH  256
#define KKC  4
#define BSR  (BB*SS)          // 8192 rows
#define EPS  1e-5f

// ---------------- scratch (static device memory; rewritten every call) ----------
__device__ __half g_xn16[BSR*EE];         // fp16 LN out (up GEMM A)
__device__ __half g_up16[BSR*2048];       // fp16 up out: x_m cols [0,1024), z cols [1024,2048)
__device__ float g_cact[BSR*II];          // fp32 (headgate skip)
__device__ __half g_ca16[BSR*II];         // fp16 conv act (qk GEMM A)
__device__ __half g_qk16[BSR*2048];       // fp16 q|k (attn + gates), stride 2048
__device__ __half g_v16[BSR*II];          // fp16 v (vtrans + gates)
__device__ float g_h   [BSR*II];          // attn out (fp32)
__device__ __half g_h16[BSR*II];          // headgate out (down GEMM A)
__device__ float g_x1  [BSR*EE];          // fp32 residual stream
__device__ __half g_x116[BSR*EE];         // fp16 copy (fin GEMM A)
__device__ float g_ipre[BB*HH*SS];
__device__ float g_fpre[BB*HH*SS];
__device__ float g_u   [BB*HH*SS];
__device__ float g_mx  [BB*HH*SS];
__device__ float g_mm  [BB*HH*SS];
__device__ __half g_vT [32*256*1024];     // V^T per (b,h), fp16 (16MB)
__device__ __half g_w16[9502720];         // fp16 weights, transposed layouts

__device__ __forceinline__ uint32_t smem_u32(const void* p) {
    uint32_t a;
    asm("{ .reg .u64 t; cvta.to.shared.u64 t, %1; cvt.u32.u64 %0, t; }" : "=r"(a) : "l"(p));
    return a;
}
__device__ __forceinline__ void cp_async16(uint32_t dst, const void* src) {
    asm volatile("cp.async.cg.shared.global [%0], [%1], 16;" :: "r"(dst), "l"(src));
}
#define CP_COMMIT() asm volatile("cp.async.commit_group;" ::: "memory")
#define CP_WAIT1()  asm volatile("cp.async.wait_group 1;"  ::: "memory")
#define CP_WAIT0()  asm volatile("cp.async.wait_group 0;"  ::: "memory")

__device__ __forceinline__ void mma_f16(float* d, const uint32_t* a, uint32_t b0, uint32_t b1) {
    asm volatile("mma.sync.aligned.m16n8k16.row.col.f32.f16.f16.f32 "
        "{%0,%1,%2,%3}, {%4,%5,%6,%7}, {%8,%9}, {%0,%1,%2,%3};"
        : "+f"(d[0]), "+f"(d[1]), "+f"(d[2]), "+f"(d[3])
        : "r"(a[0]), "r"(a[1]), "r"(a[2]), "r"(a[3]), "r"(b0), "r"(b1));
}
#define LDSM_X4(r, addr) \
    asm volatile("ldmatrix.sync.aligned.m8n8.x4.shared.b16 {%0,%1,%2,%3}, [%4];" \
        : "=r"((r)[0]), "=r"((r)[1]), "=r"((r)[2]), "=r"((r)[3]) : "r"(addr))

// ================= fp16 mma.sync GEMM, cp.async 3-stage, ldmatrix ==============
__device__ __forceinline__ uint32_t sw_off(int r, int c) {
    return (uint32_t)(((r >> 1) << 7) + (((((r & 1) << 2) + c) ^ ((r >> 1) & 7)) << 4));
}

__device__ __forceinline__ void issue_tile16(uint32_t sA, uint32_t sB,
        const __half* A, int lda, const __half* BT, int ldb,
        int row0, int col0, int k0, int tid)
{
    const __half* Ag = A + (size_t)row0 * lda + k0;
    const __half* Bg = BT + (size_t)col0 * ldb + k0;
    #pragma unroll
    for (int j = 0; j < 2; j++) {
        int i = tid + 256 * j;
        int r = i >> 2, c = i & 3;
        cp_async16(sA + sw_off(r, c), Ag + (size_t)r * lda + (c << 3));
    }
    #pragma unroll
    for (int j = 0; j < 2; j++) {
        int i = tid + 256 * j;
        int r = i >> 2, c = i & 3;
        cp_async16(sB + sw_off(r, c), Bg + (size_t)r * ldb + (c << 3));
    }
}

__device__ __forceinline__ void compute_tile16(uint32_t sA, uint32_t sB,
        float d[4][4][4], int warp_m, int warp_n, int lane)
{
    int aRow = lane & 15, aCs = lane >> 4;
    int bRow = (lane & 7) | ((lane >> 1) & 8), bCs = (lane >> 3) & 1;
    uint32_t aBase = sA + (uint32_t)(warp_m * 4096) + sw_off(aRow, aCs);
    uint32_t bBase = sB + (uint32_t)(warp_n * 2048) + sw_off(bRow, bCs);
    #pragma unroll
    for (int ks = 0; ks < 2; ks++) {
        uint32_t kx = (uint32_t)(ks << 5);
        uint32_t a[4][4], b[2][4];
        #pragma unroll
        for (int mf = 0; mf < 4; mf++)
            LDSM_X4(a[mf], (aBase + mf * 1024) ^ kx);
        LDSM_X4(b[0], bBase ^ kx);
        LDSM_X4(b[1], (bBase + 1024) ^ kx);
        #pragma unroll
        for (int mf = 0; mf < 4; mf++) {
            mma_f16(d[mf][0], a[mf], b[0][0], b[0][1]);
            mma_f16(d[mf][1], a[mf], b[0][2], b[0][3]);
            mma_f16(d[mf][2], a[mf], b[1][0], b[1][1]);
            mma_f16(d[mf][3], a[mf], b[1][2], b[1][3]);
        }
    }
}

#define GEMM_SMEM (3 * 16384)

__global__ __launch_bounds__(256) void hgemm_kernel(
    const __half* __restrict__ A, int lda,
    const __half* __restrict__ BT, int ldb,   // [N,K]
    float* __restrict__ C, int ldc, int K,
    const float* __restrict__ bias,
    const float* __restrict__ res, int ldres,
    __half* __restrict__ C2h)
{
    extern __shared__ __align__(128) char sm[];
    uint32_t sbase = smem_u32(sm);

    int tid = threadIdx.x;
    int wid = tid >> 5, lane = tid & 31;
    int laneR = lane >> 2, laneC = lane & 3;
    int warp_m = wid & 1, warp_n = wid >> 1;
    int row0 = blockIdx.y * 128, col0 = blockIdx.x * 128;

    float d[4][4][4];
    #pragma unroll
    for (int i = 0; i < 4; i++)
        #pragma unroll
        for (int j = 0; j < 4; j++)
            #pragma unroll
            for (int u = 0; u < 4; u++) d[i][j][u] = 0.f;

    const int NK = K >> 5;

    issue_tile16(sbase, sbase + 8192, A, lda, BT, ldb, row0, col0, 0, tid);
    CP_COMMIT();
    issue_tile16(sbase + 16384, sbase + 24576, A, lda, BT, ldb, row0, col0, 32, tid);
    CP_COMMIT();

    #pragma unroll 1
    for (int kt = 0; kt < NK; kt++) {
        CP_WAIT1();
        __syncthreads();
        if (kt + 2 < NK) {
            uint32_t s = (uint32_t)((kt + 2) % 3) * 16384;
            issue_tile16(sbase + s, sbase + s + 8192,
                         A, lda, BT, ldb, row0, col0, (kt + 2) << 5, tid);
        }
        CP_COMMIT();
        uint32_t b = (uint32_t)(kt % 3) * 16384;
        compute_tile16(sbase + b, sbase + b + 8192, d, warp_m, warp_n, lane);
    }

    #pragma unroll
    for (int mf = 0; mf < 4; mf++) {
        int r = row0 + warp_m * 64 + mf * 16 + laneR;
        #pragma unroll
        for (int nf = 0; nf < 4; nf++) {
            int cc = col0 + warp_n * 32 + nf * 8 + 2 * laneC;
            float2 v0 = make_float2(d[mf][nf][0], d[mf][nf][1]);
            float2 v1 = make_float2(d[mf][nf][2], d[mf][nf][3]);
            if (bias) {
                float2 bv = *(const float2*)(bias + cc);
                v0.x += bv.x; v0.y += bv.y;
                v1.x += bv.x; v1.y += bv.y;
            }
            if (res) {
                float2 r0 = *(const float2*)(res + (size_t)r * ldres + cc);
                float2 r1 = *(const float2*)(res + (size_t)(r + 8) * ldres + cc);
                v0.x += r0.x; v0.y += r0.y;
                v1.x += r1.x; v1.y += r1.y;
            }
            if (C) {
                *(float2*)(C + (size_t)r * ldc + cc)       = v0;
                *(float2*)(C + (size_t)(r + 8) * ldc + cc) = v1;
            }
            if (C2h) {
                *(__half2*)(C2h + (size_t)r * ldc + cc)       = __floats2half2_rn(v0.x, v0.y);
                *(__half2*)(C2h + (size_t)(r + 8) * ldc + cc) = __floats2half2_rn(v1.x, v1.y);
            }
        }
    }
}

// ---------------- fused weight transpose+convert ------------------------------
__global__ __launch_bounds__(256) void wtrans_all_kernel(
    const float* __restrict__ w_up, const float* __restrict__ wq,
    const float* __restrict__ wk,  const float* __restrict__ wv,
    const float* __restrict__ w_down, const float* __restrict__ w_fin,
    __half* __restrict__ w16)
{
    int bid = blockIdx.x;
    const float* in; __half* out; int K, N, loc;
    if (bid < 9216) {
        int l = bid / 4608, r = bid % 4608;
        if (r < 1024)      { in = w_up   + (size_t)l*1048576; out = w16 + (size_t)l*1048576;                     K = 512;  N = 2048; loc = r; }
        else if (r < 2048) { in = wq     + (size_t)l*1048576; out = w16 + 2097152 + (size_t)l*2097152;           K = 1024; N = 1024; loc = r - 1024; }
        else if (r < 3072) { in = wk     + (size_t)l*1048576; out = w16 + 2097152 + (size_t)l*2097152 + 1048576; K = 1024; N = 1024; loc = r - 2048; }
        else if (r < 4096) { in = wv     + (size_t)l*1048576; out = w16 + 6291456 + (size_t)l*1048576;           K = 1024; N = 1024; loc = r - 3072; }
        else               { in = w_down + (size_t)l*524288;  out = w16 + 8388608 + (size_t)l*524288;            K = 1024; N = 512;  loc = r - 4096; }
    } else {
        in = w_fin; out = w16 + 9437184; K = 512; N = 128; loc = bid - 9216;
    }
    int nw = N >> 5;
    int nb = (loc % nw) * 32, kb = (loc / nw) * 32;
    __shared__ float t[32][33];
    int tx = threadIdx.x & 31, ty = threadIdx.x >> 5;
    #pragma unroll
    for (int j = 0; j < 32; j += 8)
        t[ty + j][tx] = in[(size_t)(kb + ty + j) * N + nb + tx];
    __syncthreads();
    #pragma unroll
    for (int j = 0; j < 32; j += 8)
        out[(size_t)(nb + ty + j) * K + kb + tx] = __float2half_rn(t[tx][ty + j]);
}

// ---------------- V transpose per (b,h): g_v16 -> g_vT[bh][d][t], fp16 ---------
__global__ __launch_bounds__(256) void vtrans_kernel(__half* __restrict__ vT)
{
    __shared__ __half t[32][36];
    int bh = blockIdx.z;
    int b = bh >> 2, h = bh & 3;
    int t0 = blockIdx.x * 32, d0 = blockIdx.y * 32;
    int tx = threadIdx.x & 31, ty = threadIdx.x >> 5;
    #pragma unroll
    for (int j = 0; j < 32; j += 8)
        t[ty + j][tx] = g_v16[(size_t)(b * SS + t0 + ty + j) * II + h * DHH + d0 + tx];
    __syncthreads();
    #pragma unroll
    for (int j = 0; j < 32; j += 8)
        vT[((size_t)bh * DHH + d0 + ty + j) * SS + t0 + tx] = t[tx][ty + j];
}

// ---------------- LayerNorm over E=512 (stores fp16) ---------------------------
__global__ __launch_bounds__(256) void ln_kernel(const float* __restrict__ x,
                                                 const float* __restrict__ g,
                                                 const float* __restrict__ b,
                                                 __half* __restrict__ y)
{
    int row = blockIdx.x;
    const float* xr = x + (size_t)row * EE;
    int c2 = threadIdx.x * 2;
    float2 xv = *(const float2*)(xr + c2);
    float s = xv.x + xv.y, s2 = xv.x*xv.x + xv.y*xv.y;
    __shared__ float sh[64];
    for (int o = 16; o; o >>= 1) {
        s  += __shfl_down_sync(0xffffffffu, s,  o);
        s2 += __shfl_down_sync(0xffffffffu, s2, o);
    }
    int wid = threadIdx.x >> 5, lane = threadIdx.x & 31;
    if (lane == 0) { sh[wid] = s; sh[32+wid] = s2; }
    __syncthreads();
    if (threadIdx.x == 0) {
        float ts = 0.f, ts2 = 0.f;
        for (int w = 0; w < 8; w++) { ts += sh[w]; ts2 += sh[32+w]; }
        sh[0] = ts; sh[32] = ts2;
    }
    __syncthreads();
    float mu  = sh[0]  * (1.f/EE);
    float var = sh[32] * (1.f/EE) - mu*mu;
    float rstd = rsqrtf(var + EPS);
    float2 gv = *(const float2*)(g + c2);
    float2 bv = *(const float2*)(b + c2);
    *(__half2*)(y + (size_t)row * EE + c2) =
        __floats2half2_rn((xv.x - mu) * rstd * gv.x + bv.x,
                          (xv.y - mu) * rstd * gv.y + bv.y);
}

// ---------------- causal depthwise conv (K=4) + SiLU, fp16 in, 4 ch/thread -----
__global__ __launch_bounds__(256) void conv_silu_kernel(const float* __restrict__ cw,
                                                        const float* __restrict__ cb)
{
    int idx = blockIdx.x * 256 + threadIdx.x;
    int c4  = (idx & 255) << 2;
    int row = idx >> 8;
    int t   = row & (SS - 1);
    const __half* base = g_up16 + (size_t)row * 2048 + c4;
    float4 acc = *(const float4*)(cb + c4);
    #pragma unroll
    for (int j = 0; j < KKC; j++) {
        int tt = t - (KKC - 1) + j;
        if (tt >= 0) {
            const __half2* xp = (const __half2*)(base + (j - (KKC - 1)) * 2048);
            float2 x01 = __half22float2(xp[0]);
            float2 x23 = __half22float2(xp[1]);
            float4 wv = *(const float4*)(cw + j * II + c4);
            acc.x = fmaf(x01.x, wv.x, acc.x);
            acc.y = fmaf(x01.y, wv.y, acc.y);
            acc.z = fmaf(x23.x, wv.z, acc.z);
            acc.w = fmaf(x23.y, wv.w, acc.w);
        }
    }
    float4 sv;
    sv.x = acc.x / (1.f + __expf(-acc.x));
    sv.y = acc.y / (1.f + __expf(-acc.y));
    sv.z = acc.z / (1.f + __expf(-acc.z));
    sv.w = acc.w / (1.f + __expf(-acc.w));
    size_t o = (size_t)row * II + c4;
    *(float4*)(g_cact + o) = sv;
    __half2* p = (__half2*)(g_ca16 + o);
    p[0] = __floats2half2_rn(sv.x, sv.y);
    p[1] = __floats2half2_rn(sv.z, sv.w);
}

// ---------------- gate projections: 16 rows/block, transposed smem weights -----
#define GROWS 16
#define GATES_SMEM 98304
__global__ __launch_bounds__(256) void gates_kernel(const float* __restrict__ wi,
                                                    const float* __restrict__ bi,
                                                    const float* __restrict__ wf,
                                                    const float* __restrict__ bf)
{
    extern __shared__ __align__(16) float wsm[];   // [8][3072]
    int tid = threadIdx.x;
    const float4* wi4 = (const float4*)wi;
    const float4* wf4 = (const float4*)wf;
    for (int i = tid; i < 3072; i += 256) {
        float4 a = wi4[i];
        wsm[i]           = a.x;
        wsm[3072 + i]    = a.y;
        wsm[6144 + i]    = a.z;
        wsm[9216 + i]    = a.w;
        float4 f = wf4[i];
        wsm[12288 + i]   = f.x;
        wsm[15360 + i]   = f.y;
        wsm[18432 + i]   = f.z;
        wsm[21504 + i]   = f.w;
    }
    __syncthreads();

    int d = tid << 2;
    int lane = tid & 31, wid = tid >> 5;
    __shared__ float red[64];

    #pragma unroll 1
    for (int rl = 0; rl < GROWS; rl++) {
        int row = blockIdx.x * GROWS + rl;
        const __half2* qh = (const __half2*)(g_qk16 + (size_t)row * 2048 + d);
        const __half2* kh = (const __half2*)(g_qk16 + (size_t)row * 2048 + 1024 + d);
        const __half2* vh = (const __half2*)(g_v16 + (size_t)row * II + d);
        float2 q01 = __half22float2(qh[0]), q23 = __half22float2(qh[1]);
        float2 k01 = __half22float2(kh[0]), k23 = __half22float2(kh[1]);
        float2 v01 = __half22float2(vh[0]), v23 = __half22float2(vh[1]);
        float qa[4] = {q01.x, q01.y, q23.x, q23.y};
        float ka[4] = {k01.x, k01.y, k23.x, k23.y};
        float va[4] = {v01.x, v01.y, v23.x, v23.y};
        float acc[8];
        #pragma unroll
        for (int g = 0; g < 8; g++) {
            const float* wg = wsm + g * 3072;
            float4 wq = *(const float4*)(wg + d);
            float4 wk = *(const float4*)(wg + 1024 + d);
            float4 wv = *(const float4*)(wg + 2048 + d);
            float x;
            x  = qa[0]*wq.x + qa[1]*wq.y + qa[2]*wq.z + qa[3]*wq.w;
            x += ka[0]*wk.x + ka[1]*wk.y + ka[2]*wk.z + ka[3]*wk.w;
            x += va[0]*wv.x + va[1]*wv.y + va[2]*wv.z + va[3]*wv.w;
            acc[g] = x;
        }
        #pragma unroll
        for (int s = 0; s < 8; s++) {
            float x = acc[s];
            for (int o = 16; o; o >>= 1) x += __shfl_down_sync(0xffffffffu, x, o);
            if (lane == 0) red[s * 8 + wid] = x;
        }
        __syncthreads();
        if (tid < 64) {
            float x = red[tid];
            x += __shfl_down_sync(0xffffffffu, x, 4, 8);
            x += __shfl_down_sync(0xffffffffu, x, 2, 8);
            x += __shfl_down_sync(0xffffffffu, x, 1, 8);
            if ((tid & 7) == 0) {
                int s = tid >> 3;
                int b = row >> 10, t = row & (SS - 1);
                if (s < 4) g_ipre[((size_t)b*HH + s)     * SS + t] = x + bi[s];
                else       g_fpre[((size_t)b*HH + (s-4)) * SS + t] = x + bf[s-4];
            }
        }
        __syncthreads();
    }
}

// ---------------- gate scan (warp-shuffle): lfc, u, M, m ------------------------
__global__ __launch_bounds__(1024) void cumsum_kernel()
{
    int bh = blockIdx.x;
    int t  = threadIdx.x;
    int lane = t & 31, wd = t >> 5;
    float f  = g_fpre[bh * SS + t];
    float lf = (f > 0.f) ? -log1pf(__expf(-f)) : f - log1pf(__expf(f));

    float v = lf;
    #pragma unroll
    for (int o = 1; o < 32; o <<= 1) {
        float n = __shfl_up_sync(0xffffffffu, v, o);
        if (lane >= o) v += n;
    }
    __shared__ float ws[32], wm[32];
    if (lane == 31) ws[wd] = v;
    __syncthreads();
    if (wd == 0) {
        float w = ws[lane];
        #pragma unroll
        for (int o = 1; o < 32; o <<= 1) {
            float n = __shfl_up_sync(0xffffffffu, w, o);
            if (lane >= o) w += n;
        }
        ws[lane] = w;
    }
    __syncthreads();
    float lfc = v + (wd > 0 ? ws[wd - 1] : 0.f);
    float u = g_ipre[bh * SS + t] - lfc;
    g_u[bh * SS + t] = u;

    float m = u;
    #pragma unroll
    for (int o = 1; o < 32; o <<= 1) {
        float n = __shfl_up_sync(0xffffffffu, m, o);
        if (lane >= o) m = fmaxf(m, n);
    }
    if (lane == 31) wm[wd] = m;
    __syncthreads();
    if (wd == 0) {
        float w = wm[lane];
        #pragma unroll
        for (int o = 1; o < 32; o <<= 1) {
            float n = __shfl_up_sync(0xffffffffu, w, o);
            if (lane >= o) w = fmaxf(w, n);
        }
        wm[lane] = w;
    }
    __syncthreads();
    float M = (wd > 0) ? fmaxf(m, wm[wd - 1]) : m;
    g_mx[bh * SS + t] = M;
    g_mm[bh * SS + t] = lfc + M;
}

// ---------------- fp16 attention, double-buffered K/V/u ------------------------
// Qs 0..32K | Ks0 32K | Ks1 64K | Vs0 96K | Vs1 128K | Ps 160K(8K) | u0/u1 | ss
#define OFF_KS0  32768
#define OFF_VS0  98304
#define OFF_PS   163840
#define OFF_U0   172032
#define OFF_SS   172544
#define ATT3_SMEM 173568

__device__ __forceinline__ void attn_issue_kv(uint32_t sb2, int buf, int s0,
        size_t qkbase, const __half* vTb, const float* uptr, int tid)
{
    uint32_t ks = (uint32_t)(OFF_KS0 + buf * 32768);
    uint32_t vs = (uint32_t)(OFF_VS0 + buf * 32768);
    #pragma unroll
    for (int j = 0; j < 8; j++) {
        int i = tid + 256 * j;
        int r = i >> 5, c = i & 31;
        cp_async16(sb2 + ks + r * 512 + ((c ^ (r & 7)) << 4),
                   g_qk16 + qkbase + 1024 + (size_t)(s0 + r) * 2048 + (c << 3));
    }
    #pragma unroll
    for (int j = 0; j < 8; j++) {
        int i = tid + 256 * j;
        int r = i >> 3, c = i & 7;
        cp_async16(sb2 + vs + (r << 7) + ((c ^ (r & 7)) << 4),
                   vTb + (size_t)r * SS + s0 + (c << 3));
    }
    if (tid < 16)
        cp_async16(sb2 + (uint32_t)(OFF_U0 + buf * 256) + tid * 16, uptr + s0 + tid * 4);
}

__global__ __launch_bounds__(256) void attn3_kernel(const __half* __restrict__ vT)
{
    extern __shared__ __align__(128) char sm2[];
    float* ss_sh = (float*)(sm2 + OFF_SS);
    uint32_t sb2 = smem_u32(sm2);

    int bh = blockIdx.x;
    int tb = (int)gridDim.y - 1 - (int)blockIdx.y;
    int b = bh >> 2, h = bh & 3;
    int tid = threadIdx.x;
    int wid = tid >> 5, lane = tid & 31;
    int laneR = lane >> 2, laneC = lane & 3;
    int warp_m = wid & 1, warp_n = wid >> 1;
    int t0 = tb * 64;
    size_t qkbase = ((size_t)b * SS) * 2048 + (size_t)h * DHH;
    size_t obase  = ((size_t)b * SS) * II + (size_t)h * DHH;
    const __half* vTb = vT + (size_t)bh * DHH * SS;
    const float* uptr = g_u + bh * SS;

    // group 0: Q tile + KV(0) + u(0)
    #pragma unroll
    for (int j = 0; j < 8; j++) {
        int i = tid + 256 * j;
        int r = i >> 5, c = i & 31;
        cp_async16(sb2 + r * 512 + ((c ^ (r & 7)) << 4),
                   g_qk16 + qkbase + (size_t)(t0 + r) * 2048 + (c << 3));
    }
    attn_issue_kv(sb2, 0, 0, qkbase, vTb, uptr, tid);
    CP_COMMIT();

    float Mr[4], ssum[4];
    #pragma unroll
    for (int k = 0; k < 4; k++) {
        int row = warp_m * 32 + (k >> 1) * 16 + (k & 1) * 8 + laneR;
        Mr[k] = g_mx[bh * SS + t0 + row];
        ssum[k] = 0.f;
    }

    float o[2][8][4];
    #pragma unroll
    for (int mf = 0; mf < 2; mf++)
        #pragma unroll
        for (int nf = 0; nf < 8; nf++)
            #pragma unroll
            for (int u = 0; u < 4; u++) o[mf][nf][u] = 0.f;

    int aRow = (lane & 15);
    int aSel = lane >> 4;
    int bRow = (lane & 7) | ((lane >> 1) & 8);
    int bSel = (lane >> 3) & 1;

    #pragma unroll 1
    for (int sb = 0; sb <= tb; sb++) {
        int buf = sb & 1;
        int s0 = sb * 64;
        if (sb < tb) {
            attn_issue_kv(sb2, buf ^ 1, s0 + 64, qkbase, vTb, uptr, tid);
            CP_COMMIT();
            CP_WAIT1();
        } else {
            CP_WAIT0();
        }
        __syncthreads();

        const float* u_sh = (const float*)(sm2 + OFF_U0 + buf * 256);

        // ---- GEMM1: S = Q K^T ----
        float s8[2][2][4];
        #pragma unroll
        for (int mf = 0; mf < 2; mf++)
            #pragma unroll
            for (int nf = 0; nf < 2; nf++)
                #pragma unroll
                for (int u = 0; u < 4; u++) s8[mf][nf][u] = 0.f;
        {
            int ar = warp_m * 32 + aRow;
            uint32_t aBase0 = sb2 + ar * 512;
            uint32_t aBase1 = aBase0 + 16 * 512;
            uint32_t axr = (uint32_t)(ar & 7);
            int br = warp_n * 16 + bRow;
            uint32_t bBase = sb2 + (uint32_t)(OFF_KS0 + buf * 32768) + br * 512;
            uint32_t bxr = (uint32_t)(br & 7);
            #pragma unroll
            for (int ks = 0; ks < 16; ks++) {
                uint32_t ca = (uint32_t)(2 * ks + aSel) ^ axr;
                uint32_t cb = (uint32_t)(2 * ks + bSel) ^ bxr;
                uint32_t a0[4], a1[4], bq[4];
                LDSM_X4(a0, aBase0 + (ca << 4));
                LDSM_X4(a1, aBase1 + (ca << 4));
                LDSM_X4(bq, bBase + (cb << 4));
                mma_f16(s8[0][0], a0, bq[0], bq[1]);
                mma_f16(s8[0][1], a0, bq[2], bq[3]);
                mma_f16(s8[1][0], a1, bq[0], bq[1]);
                mma_f16(s8[1][1], a1, bq[2], bq[3]);
            }
        }

        // ---- weights + mask -> P (fp16) + running score sums ----
        bool diag = (sb == tb);
        #pragma unroll
        for (int mf = 0; mf < 2; mf++) {
            #pragma unroll
            for (int e = 0; e < 2; e++) {
                int row = warp_m * 32 + mf * 16 + e * 8 + laneR;
                int tg = t0 + row;
                float M = Mr[mf * 2 + e];
                #pragma unroll
                for (int nf = 0; nf < 2; nf++) {
                    int cb = warp_n * 16 + nf * 8 + 2 * laneC;
                    float d0 = s8[mf][nf][2 * e] * 0.0625f;
                    float d1 = s8[mf][nf][2 * e + 1] * 0.0625f;
                    float w0 = (!diag || (s0 + cb)     <= tg) ? __expf(u_sh[cb]     - M) : 0.f;
                    float w1 = (!diag || (s0 + cb + 1) <= tg) ? __expf(u_sh[cb + 1] - M) : 0.f;
                    __half2 pk = __floats2half2_rn(d0 * w0, d1 * w1);
                    ssum[mf * 2 + e] += __low2float(pk) + __high2float(pk);
                    *(__half2*)(sm2 + OFF_PS + (row << 7)
                                + (((cb >> 3) ^ (row & 7)) << 4) + ((cb & 7) << 1)) = pk;
                }
            }
        }
        __syncthreads();

        // ---- GEMM2: O += P Vs ----
        {
            int ar = warp_m * 32 + aRow;
            uint32_t aBase0 = sb2 + OFF_PS + (ar << 7);
            uint32_t aBase1 = aBase0 + (16 << 7);
            uint32_t axr = (uint32_t)(ar & 7);
            uint32_t vs = (uint32_t)(OFF_VS0 + buf * 32768);
            uint32_t bB[4], bxr[4];
            #pragma unroll
            for (int nf2 = 0; nf2 < 4; nf2++) {
                int br = warp_n * 64 + nf2 * 16 + bRow;
                bB[nf2] = sb2 + vs + (br << 7);
                bxr[nf2] = (uint32_t)(br & 7);
            }
            #pragma unroll
            for (int ks = 0; ks < 4; ks++) {
                uint32_t ca = ((uint32_t)(2 * ks + aSel) ^ axr) << 4;
                uint32_t a0[4], a1[4];
                LDSM_X4(a0, aBase0 + ca);
                LDSM_X4(a1, aBase1 + ca);
                #pragma unroll
                for (int nf2 = 0; nf2 < 4; nf2++) {
                    uint32_t cb = ((uint32_t)(2 * ks + bSel) ^ bxr[nf2]) << 4;
                    uint32_t bq[4];
                    LDSM_X4(bq, bB[nf2] + cb);
                    mma_f16(o[0][nf2 * 2],     a0, bq[0], bq[1]);
                    mma_f16(o[0][nf2 * 2 + 1], a0, bq[2], bq[3]);
                    mma_f16(o[1][nf2 * 2],     a1, bq[0], bq[1]);
                    mma_f16(o[1][nf2 * 2 + 1], a1, bq[2], bq[3]);
                }
            }
        }
        __syncthreads();   // protect buf from next iteration's prefetch
    }

    // ---- epilogue ----
    #pragma unroll
    for (int k = 0; k < 4; k++) {
        ssum[k] += __shfl_xor_sync(0xffffffffu, ssum[k], 1);
        ssum[k] += __shfl_xor_sync(0xffffffffu, ssum[k], 2);
    }
    if (laneC == 0) {
        #pragma unroll
        for (int k = 0; k < 4; k++) {
            int row = warp_m * 32 + (k >> 1) * 16 + (k & 1) * 8 + laneR;
            ss_sh[warp_n * 64 + row] = ssum[k];
        }
    }
    __syncthreads();
    float inv[4];
    #pragma unroll
    for (int k = 0; k < 4; k++) {
        int row = warp_m * 32 + (k >> 1) * 16 + (k & 1) * 8 + laneR;
        float tot = ss_sh[row] + ss_sh[64 + row] + ss_sh[128 + row] + ss_sh[192 + row];
        float mm = g_mm[bh * SS + t0 + row];
        inv[k] = 1.f / fmaxf(fabsf(tot), __expf(-mm));
    }
    #pragma unroll
    for (int mf = 0; mf < 2; mf++) {
        int r0 = t0 + warp_m * 32 + mf * 16 + laneR;
        float i0 = inv[mf * 2], i1 = inv[mf * 2 + 1];
        #pragma unroll
        for (int nf = 0; nf < 8; nf++) {
            int c = warp_n * 64 + nf * 8 + 2 * laneC;
            *(float2*)(g_h + obase + (size_t)r0 * II + c) =
                make_float2(o[mf][nf][0] * i0, o[mf][nf][1] * i0);
            *(float2*)(g_h + obase + (size_t)(r0 + 8) * II + c) =
                make_float2(o[mf][nf][2] * i1, o[mf][nf][3] * i1);
        }
    }
}

// ---------------- per-head norm + gate, 1 sync, float4 (stores fp16) -----------
__global__ __launch_bounds__(256) void headgate_kernel(const float* __restrict__ gn,
                                                       const float* __restrict__ sk)
{
    int row = blockIdx.x;
    int tid = threadIdx.x;
    int wid = tid >> 5, lane = tid & 31;
    int h = wid >> 1;
    int c = h * DHH + (wid & 1) * 128 + lane * 4;
    size_t base = (size_t)row * II;
    float4 v = *(const float4*)(g_h + base + c);
    float s  = v.x + v.y + v.z + v.w;
    float s2 = v.x*v.x + v.y*v.y + v.z*v.z + v.w*v.w;
    for (int o = 16; o; o >>= 1) {
        s  += __shfl_down_sync(0xffffffffu, s,  o);
        s2 += __shfl_down_sync(0xffffffffu, s2, o);
    }
    __shared__ float sh[16];
    if (lane == 0) { sh[wid] = s; sh[8 + wid] = s2; }
    __syncthreads();
    float ts  = sh[h*2]     + sh[h*2 + 1];
    float ts2 = sh[8 + h*2] + sh[8 + h*2 + 1];
    float mu  = ts  * (1.f/DHH);
    float var = ts2 * (1.f/DHH) - mu*mu;
    float rstd = rsqrtf(var + EPS);
    float4 gn4 = *(const float4*)(gn + c);
    float4 sk4 = *(const float4*)(sk + c);
    float4 ca4 = *(const float4*)(g_cact + base + c);
    const __half2* zp = (const __half2*)(g_up16 + (size_t)row * 2048 + II + c);
    float2 z01 = __half22float2(zp[0]);
    float2 z23 = __half22float2(zp[1]);
    float zz[4] = {z01.x, z01.y, z23.x, z23.y};
    float hn[4];
    hn[0] = (v.x - mu) * rstd * gn4.x + sk4.x * ca4.x;
    hn[1] = (v.y - mu) * rstd * gn4.y + sk4.y * ca4.y;
    hn[2] = (v.z - mu) * rstd * gn4.z + sk4.z * ca4.z;
    hn[3] = (v.w - mu) * rstd * gn4.w + sk4.w * ca4.w;
    #pragma unroll
    for (int j = 0; j < 4; j++)
        hn[j] *= zz[j] / (1.f + __expf(-zz[j]));
    __half2* p = (__half2*)(g_h16 + base + c);
    p[0] = __floats2half2_rn(hn[0], hn[1]);
    p[1] = __floats2half2_rn(hn[2], hn[3]);
}

// ------------------------------- host -----------------------------------------
#define W16_UP(l)   (w16 + (size_t)(l)*1048576)
#define W16_QK(l)   (w16 + 2097152 + (size_t)(l)*2097152)
#define W16_V(l)    (w16 + 6291456 + (size_t)(l)*1048576)
#define W16_DOWN(l) (w16 + 8388608 + (size_t)(l)*524288)
#define W16_FIN     (w16 + 9437184)

static inline void launch_gemm(const __half* A, int lda, const __half* BT, int ldb,
                               float* C, int ldc, int M, int N, int K,
                               const float* bias, const float* res, int ldres,
                               __half* C2h = nullptr)
{
    dim3 grid(N / 128, M / 128);
    hgemm_kernel<<<grid, 256, GEMM_SMEM>>>(A, lda, BT, ldb, C, ldc, K,
                                           bias, res, ldres, C2h);
}

extern "C" void kernel_launch(void* const* d_in, const int* in_sizes, int n_in,
                              void* d_out, int out_size)
{
    (void)in_sizes; (void)n_in; (void)out_size;
    const float* x      = (const float*)d_in[0];
    const float* ln_g   = (const float*)d_in[1];
    const float* ln_b   = (const float*)d_in[2];
    const float* w_up   = (const float*)d_in[3];
    const float* conv_w = (const float*)d_in[4];
    const float* conv_b = (const float*)d_in[5];
    const float* wq     = (const float*)d_in[6];
    const float* wk     = (const float*)d_in[7];
    const float* wv     = (const float*)d_in[8];
    const float* w_i    = (const float*)d_in[9];
    const float* b_i    = (const float*)d_in[10];
    const float* w_f    = (const float*)d_in[11];
    const float* b_f    = (const float*)d_in[12];
    const float* skip   = (const float*)d_in[13];
    const float* gn_g   = (const float*)d_in[14];
    const float* w_down = (const float*)d_in[15];
    const float* b_down = (const float*)d_in[16];
    const float* w_fin  = (const float*)d_in[17];
    const float* b_fin  = (const float*)d_in[18];

    float *x1;
    __half *xn16, *up16, *ca16, *qk16, *h16, *x116, *w16, *vT, *v16;
    cudaGetSymbolAddress((void**)&xn16, g_xn16);
    cudaGetSymbolAddress((void**)&up16, g_up16);
    cudaGetSymbolAddress((void**)&ca16, g_ca16);
    cudaGetSymbolAddress((void**)&qk16, g_qk16);
    cudaGetSymbolAddress((void**)&h16,  g_h16);
    cudaGetSymbolAddress((void**)&x1,   g_x1);
    cudaGetSymbolAddress((void**)&x116, g_x116);
    cudaGetSymbolAddress((void**)&w16,  g_w16);
    cudaGetSymbolAddress((void**)&vT,   g_vT);
    cudaGetSymbolAddress((void**)&v16,  g_v16);

    cudaFuncSetAttribute(hgemm_kernel, cudaFuncAttributeMaxDynamicSharedMemorySize,
                         GEMM_SMEM);
    cudaFuncSetAttribute(attn3_kernel, cudaFuncAttributeMaxDynamicSharedMemorySize,
                         ATT3_SMEM);
    cudaFuncSetAttribute(gates_kernel, cudaFuncAttributeMaxDynamicSharedMemorySize,
                         GATES_SMEM);

    // weights -> fp16 transposed, single fused launch (q|k packed per layer)
    wtrans_all_kernel<<<9280, 256>>>(w_up, wq, wk, wv, w_down, w_fin, w16);

    const float* cur = x;
    for (int l = 0; l < 2; l++) {
        ln_kernel<<<BSR, 256>>>(cur, ln_g + l*EE, ln_b + l*EE, xn16);
        launch_gemm(xn16, EE, W16_UP(l), EE, nullptr, 2048, BSR, 2048, EE,
                    nullptr, nullptr, 0, up16);
        conv_silu_kernel<<<(BSR*II)/1024, 256>>>(conv_w + l*KKC*II, conv_b + l*II);
        launch_gemm(ca16, II, W16_QK(l), II, nullptr, 2048, BSR, 2048, II,
                    nullptr, nullptr, 0, qk16);
        launch_gemm(up16, 2048, W16_V(l), II, nullptr, II, BSR, II, II,
                    nullptr, nullptr, 0, v16);
        gates_kernel<<<BSR/GROWS, 256, GATES_SMEM>>>(
            w_i + (size_t)l*3*II*HH, b_i + l*HH,
            w_f + (size_t)l*3*II*HH, b_f + l*HH);
        cumsum_kernel<<<BB*HH, SS>>>();
        vtrans_kernel<<<dim3(SS/32, DHH/32, BB*HH), 256>>>(vT);
        attn3_kernel<<<dim3(BB*HH, SS/64), 256, ATT3_SMEM>>>(vT);
        headgate_kernel<<<BSR, 256>>>(gn_g + l*II, skip + l*II);
        launch_gemm(h16, II, W16_DOWN(l), II, x1, EE, BSR, EE, II,
                    b_down + l*EE, cur, EE, x116);
        cur = x1;
    }
    // final: (8192,512)@(512,128) + b_fin
    launch_gemm(x116, EE, W16_FIN, EE, (float*)d_out, 128, BSR, 128, EE,
                b_fin, nullptr, 0);
}